// round 10
// baseline (speedup 1.0000x reference)
#include <cuda_runtime.h>
#include <cuda_bf16.h>
#include <cstdint>

#define NB   8
#define NC   512
#define NHW  1024
#define NH   8
#define HD   64
#define NG   32
#define CPG  16

// -------- scratch (static device arrays; no cudaMalloc allowed) --------
__device__ float g_xn [NB*NC*NHW];              // 16 MB  groupnorm output (fp32)
__device__ float g_qkv[NB*3*NC*NHW];            // 48 MB  qkv activations (fp32)
__device__ float g_att[NB*NC*NHW];              // 16 MB  attention output (fp32)
__device__ __nv_bfloat16 g_wA[3*NC*2*NC];       //  3 MB  qkv_w  hi|lo  [1536][1024]
__device__ __nv_bfloat16 g_wP[NC*2*NC];         //  1 MB  proj_w hi|lo  [512][1024]
__device__ __nv_bfloat16 g_xT[NB*NHW*2*NC];     // 16 MB  xn^T hi|lo / QT [bh][1024][128]
__device__ __nv_bfloat16 g_aT[NB*NHW*2*NC];     // 16 MB  KT [bh][1024][128] / att^T hi|lo
__device__ __nv_bfloat16 g_vc[NB*NH*2*HD*NHW];  // 16 MB  V hi|lo planes [bh][128][1024]

// -------- mma.sync / cp.async helpers (arch-generic) --------
__device__ __forceinline__ uint32_t smem_u32(const void* p){
    uint32_t a;
    asm("{ .reg .u64 t; cvta.to.shared.u64 t, %1; cvt.u32.u64 %0, t; }"
        : "=r"(a) : "l"(p));
    return a;
}
__device__ __forceinline__ void ldmx4(uint32_t* r, uint32_t addr){
    asm volatile("ldmatrix.sync.aligned.m8n8.x4.shared.b16 {%0,%1,%2,%3}, [%4];"
        : "=r"(r[0]),"=r"(r[1]),"=r"(r[2]),"=r"(r[3]) : "r"(addr));
}
__device__ __forceinline__ void ldmx2(uint32_t* r, uint32_t addr){
    asm volatile("ldmatrix.sync.aligned.m8n8.x2.shared.b16 {%0,%1}, [%2];"
        : "=r"(r[0]),"=r"(r[1]) : "r"(addr));
}
__device__ __forceinline__ void mma16816(float* d, const uint32_t* a, const uint32_t* b){
    asm volatile("mma.sync.aligned.m16n8k16.row.col.f32.bf16.bf16.f32 "
        "{%0,%1,%2,%3}, {%4,%5,%6,%7}, {%8,%9}, {%0,%1,%2,%3};"
        : "+f"(d[0]),"+f"(d[1]),"+f"(d[2]),"+f"(d[3])
        : "r"(a[0]),"r"(a[1]),"r"(a[2]),"r"(a[3]), "r"(b[0]),"r"(b[1]));
}
__device__ __forceinline__ void cpa16(uint32_t s, const void* g){
    asm volatile("cp.async.cg.shared.global [%0], [%1], 16;" :: "r"(s), "l"(g));
}
#define CP_COMMIT() asm volatile("cp.async.commit_group;" ::: "memory")
#define CP_WAIT0()  asm volatile("cp.async.wait_group 0;" ::: "memory")

// ============================================================================
// GroupNorm (validated)
// ============================================================================
__global__ void __launch_bounds__(256)
gn_kernel(const float* __restrict__ x,
          const float* __restrict__ gw,
          const float* __restrict__ gb)
{
    const int GSZ4 = CPG*NHW/4;
    int bg = blockIdx.x;
    int g  = bg & (NG-1);
    const float4* xp = (const float4*)(x + (size_t)bg*CPG*NHW);
    float4*       op = (float4*)(g_xn + (size_t)bg*CPG*NHW);

    float s = 0.f, s2 = 0.f;
    for (int i = threadIdx.x; i < GSZ4; i += 256){
        float4 v = xp[i];
        s  += (v.x+v.y)+(v.z+v.w);
        s2 += (v.x*v.x+v.y*v.y)+(v.z*v.z+v.w*v.w);
    }
    #pragma unroll
    for (int m=16;m;m>>=1){
        s  += __shfl_xor_sync(0xffffffffu, s,  m);
        s2 += __shfl_xor_sync(0xffffffffu, s2, m);
    }
    __shared__ float shA[8], shB[8], shMu, shRs;
    int w = threadIdx.x>>5, l = threadIdx.x&31;
    if (l==0){ shA[w]=s; shB[w]=s2; }
    __syncthreads();
    if (threadIdx.x==0){
        float S=0.f, S2=0.f;
        #pragma unroll
        for (int i=0;i<8;i++){ S+=shA[i]; S2+=shB[i]; }
        const float inv = 1.f/(float)(CPG*NHW);
        float mu  = S*inv;
        float var = S2*inv - mu*mu;
        shMu = mu; shRs = rsqrtf(var + 1e-5f);
    }
    __syncthreads();
    float mu = shMu, rstd = shRs;
    for (int i = threadIdx.x; i < GSZ4; i += 256){
        float4 v = xp[i];
        int cl = i >> 8;
        float a = gw[g*CPG+cl]*rstd;
        float c = gb[g*CPG+cl] - mu*a;
        float4 o;
        o.x=v.x*a+c; o.y=v.y*a+c; o.z=v.z*a+c; o.w=v.w*a+c;
        op[i]=o;
    }
}

// ============================================================================
// Weight converter: fp32 [M][512] -> bf16 hi|lo [M][1024]
// ============================================================================
__global__ void __launch_bounds__(256)
conv_w_kernel(const float* __restrict__ w, __nv_bfloat16* __restrict__ o, int total)
{
    int i = (blockIdx.x*256 + threadIdx.x)*4;
    if (i >= total) return;
    float4 v = *(const float4*)(w + i);
    int m = i >> 9, k = i & 511;
    __nv_bfloat16* row = o + (size_t)m*1024;
    float a[4] = {v.x, v.y, v.z, v.w};
    #pragma unroll
    for (int j=0;j<4;j++){
        __nv_bfloat16 h = __float2bfloat16(a[j]);
        row[k+j]       = h;
        row[512+k+j]   = __float2bfloat16(a[j] - __bfloat162float(h));
    }
}

// ============================================================================
// Activation transpose-converter: fp32 [z][512 k][1024 n] -> bf16 hi|lo
// [z][1024 n][1024 (k|k+512)]
// ============================================================================
__global__ void __launch_bounds__(256)
conv_actT_kernel(const float* __restrict__ in, __nv_bfloat16* __restrict__ out)
{
    __shared__ float t[32][33];
    int n0 = blockIdx.x*32, k0 = blockIdx.y*32, z = blockIdx.z;
    int tx = threadIdx.x, ty = threadIdx.y;
    const float* ip = in + ((size_t)z*NC + k0)*NHW + n0;
    #pragma unroll
    for (int j=0;j<4;j++)
        t[ty*4+j][tx] = ip[(size_t)(ty*4+j)*NHW + tx];
    __syncthreads();
    __nv_bfloat16* op = out + ((size_t)z*NHW + n0)*1024 + k0;
    #pragma unroll
    for (int j=0;j<4;j++){
        int nl = ty*4+j;
        float v = t[tx][nl];
        __nv_bfloat16 h = __float2bfloat16(v);
        op[(size_t)nl*1024 + tx]       = h;
        op[(size_t)nl*1024 + 512 + tx] = __float2bfloat16(v - __bfloat162float(h));
    }
}

// ============================================================================
// Q+K transpose-converter (merged): z<64 -> Q (scale 1/8) into outQ,
// z>=64 -> K (scale 1) into outK.  out [bh][n 1024][d-hi 64|d-lo 64]
// ============================================================================
__global__ void __launch_bounds__(256)
conv_qkT_kernel(const float* __restrict__ in,
                __nv_bfloat16* __restrict__ outQ,
                __nv_bfloat16* __restrict__ outK)
{
    __shared__ float t[32][33];
    int zz = blockIdx.z;
    int isK = zz >= NB*NH;
    int bh = zz & 63;
    int b = bh >> 3, h = bh & 7;
    int coff  = isK ? NC : 0;
    float scale = isK ? 1.0f : 0.125f;
    __nv_bfloat16* out = isK ? outK : outQ;

    int n0 = blockIdx.x*32, d0 = blockIdx.y*32;
    int tx = threadIdx.x, ty = threadIdx.y;
    const float* ip = in + ((size_t)b*3*NC + coff + h*HD + d0)*NHW + n0;
    #pragma unroll
    for (int j=0;j<4;j++)
        t[ty*4+j][tx] = ip[(size_t)(ty*4+j)*NHW + tx];
    __syncthreads();
    __nv_bfloat16* op = out + ((size_t)bh*NHW + n0)*128 + d0;
    #pragma unroll
    for (int j=0;j<4;j++){
        int nl = ty*4+j;
        float v = t[tx][nl]*scale;
        __nv_bfloat16 hv = __float2bfloat16(v);
        op[(size_t)nl*128 + tx]      = hv;
        op[(size_t)nl*128 + 64 + tx] = __float2bfloat16(v - __bfloat162float(hv));
    }
}

// ============================================================================
// V converter: g_qkv V part [b][h*64+d][m] -> g_vc [bh][d|d+64][m] hi|lo planes
// ============================================================================
__global__ void __launch_bounds__(256)
conv_v_kernel(const float* __restrict__ in, __nv_bfloat16* __restrict__ out)
{
    int bh = blockIdx.y, b = bh >> 3, h = bh & 7;
    int idx = (blockIdx.x*256 + threadIdx.x)*4;
    int d = idx >> 10, m = idx & 1023;
    float4 v = *(const float4*)(in + ((size_t)b*3*NC + 2*NC + h*HD + d)*NHW + m);
    __nv_bfloat16* o = out + (size_t)bh*128*1024;
    float a[4] = {v.x, v.y, v.z, v.w};
    __nv_bfloat16 hi[4], lo[4];
    #pragma unroll
    for (int j=0;j<4;j++){
        hi[j] = __float2bfloat16(a[j]);
        lo[j] = __float2bfloat16(a[j] - __bfloat162float(hi[j]));
    }
    *(uint2*)(o + (size_t)d*1024 + m)        = *(uint2*)hi;
    *(uint2*)(o + (size_t)(d+64)*1024 + m)   = *(uint2*)lo;
}

// ============================================================================
// HMMA split GEMM, 2-stage cp.async pipeline.
// C[z][m][n] = A[m][:512]*B[z][n][:512]^T + bias[m] (+ res)
// ============================================================================
#define TPAD   72
#define TILE_E (128*TPAD)
#define STAGE_B (4*TILE_E*2)            // 4 tiles per stage (Ah,Al,Bh,Bl)
#define GEMM_SMEM (2*STAGE_B)           // 147456

__global__ void __launch_bounds__(256,1)
mma_gemm_kernel(const __nv_bfloat16* __restrict__ A2,
                const __nv_bfloat16* __restrict__ B2t,
                const float* __restrict__ bias,
                const float* __restrict__ res,
                float* __restrict__ C,
                int M)
{
    extern __shared__ __nv_bfloat16 sm[];
    const int tid  = threadIdx.x;
    const int warp = tid >> 5, lane = tid & 31;
    const int wm = warp >> 2, wn = warp & 3;
    const int n0 = blockIdx.x*128, m0 = blockIdx.y*128, z = blockIdx.z;

    const __nv_bfloat16* Ag = A2 + (size_t)m0*1024;
    const __nv_bfloat16* Bg = B2t + ((size_t)z*NHW + n0)*1024;

    const uint32_t smBase = smem_u32(sm);
    const int aOff = (wm*64 + (lane & 15))*TPAD + (lane >> 4)*8;
    const int bOff = (wn*32 + (lane & 7))*TPAD + ((lane >> 3) & 1)*8;
    const uint32_t fA = smBase + aOff*2;            // Ah at stage base + 0
    const uint32_t fB = smBase + bOff*2;            // Bh at stage base + 2*TILE_E*2

    // per-thread copy indices
    const int crow = tid >> 3, cseg = (tid & 7)*8;

    auto issue_chunk = [&](int c){
        const int st = c & 1;
        const uint32_t base = smBase + st*STAGE_B;
        const int kh = c*64, kl = 512 + c*64;
        #pragma unroll
        for (int it=0; it<4; it++){
            int row = crow + it*32;
            uint32_t so = (uint32_t)(row*TPAD + cseg)*2;
            size_t go = (size_t)row*1024 + cseg;
            cpa16(base +              so, Ag + go + kh);
            cpa16(base + TILE_E*2   + so, Ag + go + kl);
            cpa16(base + 2*TILE_E*2 + so, Bg + go + kh);
            cpa16(base + 3*TILE_E*2 + so, Bg + go + kl);
        }
        CP_COMMIT();
    };

    float acc[4][4][4];
    #pragma unroll
    for (int i=0;i<4;i++)
        #pragma unroll
        for (int j=0;j<4;j++)
            #pragma unroll
            for (int r=0;r<4;r++) acc[i][j][r]=0.f;

    issue_chunk(0);

    for (int c = 0; c < 8; c++){
        CP_WAIT0();
        __syncthreads();
        if (c < 7) issue_chunk(c+1);

        const uint32_t so = (c & 1)*STAGE_B;
        const uint32_t sAhA = fA + so,             sAlA = fA + so + TILE_E*2;
        const uint32_t sBhA = fB + so + 2*TILE_E*2, sBlA = fB + so + 3*TILE_E*2;

        #pragma unroll
        for (int k16 = 0; k16 < 4; k16++){
            const uint32_t kb = k16*32;
            uint32_t bh[4][2], bl[4][2];
            #pragma unroll
            for (int nt=0; nt<4; nt++){
                ldmx2(bh[nt], sBhA + nt*(8*TPAD*2) + kb);
                ldmx2(bl[nt], sBlA + nt*(8*TPAD*2) + kb);
            }
            #pragma unroll
            for (int mt=0; mt<4; mt++){
                uint32_t ah[4], al[4];
                ldmx4(ah, sAhA + mt*(16*TPAD*2) + kb);
                ldmx4(al, sAlA + mt*(16*TPAD*2) + kb);
                #pragma unroll
                for (int nt=0; nt<4; nt++){
                    mma16816(acc[mt][nt], ah, bh[nt]);
                    mma16816(acc[mt][nt], ah, bl[nt]);
                    mma16816(acc[mt][nt], al, bh[nt]);
                }
            }
        }
    }

    const int rBase = m0 + wm*64 + (lane >> 2);
    const int cBase = n0 + wn*32 + (lane & 3)*2;
    #pragma unroll
    for (int mt=0; mt<4; mt++){
        const int r0 = rBase + mt*16;
        const float bi0 = bias[r0], bi1 = bias[r0+8];
        float* cp0 = C + ((size_t)z*M + r0  )*NHW;
        float* cp1 = C + ((size_t)z*M + r0+8)*NHW;
        const float* rp0 = res ? res + ((size_t)z*M + r0  )*NHW : nullptr;
        const float* rp1 = res ? res + ((size_t)z*M + r0+8)*NHW : nullptr;
        #pragma unroll
        for (int nt=0; nt<4; nt++){
            const int cc = cBase + nt*8;
            float2 v0 = make_float2(acc[mt][nt][0]+bi0, acc[mt][nt][1]+bi0);
            float2 v1 = make_float2(acc[mt][nt][2]+bi1, acc[mt][nt][3]+bi1);
            if (rp0){
                float2 a0 = *(const float2*)(rp0 + cc);
                float2 a1 = *(const float2*)(rp1 + cc);
                v0.x+=a0.x; v0.y+=a0.y; v1.x+=a1.x; v1.y+=a1.y;
            }
            *(float2*)(cp0 + cc) = v0;
            *(float2*)(cp1 + cc) = v1;
        }
    }
}

// ============================================================================
// HMMA flash attention with cp.async overlap + double-buffered V.
// Block per (q-tile 128, bh). 8 warps; warp owns 16 q rows x full 128 m.
// ============================================================================
#define AST 136
#define ATE (128*AST)
#define ATT_SMEM (6*ATE*2)              // Q,K,V0,V1,Ph,Pl = 208896 B

__global__ void __launch_bounds__(256)
attn_mma_kernel(const __nv_bfloat16* __restrict__ QT,
                const __nv_bfloat16* __restrict__ KT,
                const __nv_bfloat16* __restrict__ Vc)
{
    extern __shared__ __nv_bfloat16 sm[];
    __nv_bfloat16* sQ  = sm;
    __nv_bfloat16* sK  = sm + ATE;
    __nv_bfloat16* sPh = sm + 4*ATE;
    __nv_bfloat16* sPl = sm + 5*ATE;
    const uint32_t sV0a = smem_u32(sm + 2*ATE);
    const uint32_t sV1a = smem_u32(sm + 3*ATE);

    const int tid = threadIdx.x, warp = tid >> 5, lane = tid & 31;
    const int q0 = blockIdx.x*128, bh = blockIdx.y;
    const int qrow = warp*16;

    const __nv_bfloat16* Qg = QT + ((size_t)bh*NHW + q0)*128;
    const __nv_bfloat16* Kg = KT + (size_t)bh*NHW*128;
    const __nv_bfloat16* Vg = Vc + (size_t)bh*128*1024;

    const uint32_t sQa = smem_u32(sQ), sKa = smem_u32(sK);
    const int crow = tid >> 1, cseg = (tid & 1)*8;   // 2 threads x 16B = 32B/row? no:
    // copy indexing: 256 threads, 8 iters, each 16B: i = tid + it*256; row=i>>4; seg=(i&15)*8
    auto issueK = [&](int mm0){
        #pragma unroll
        for (int it=0; it<8; it++){
            int i = tid + it*256;
            int row = i >> 4, seg = (i & 15)*8;
            cpa16(sKa + (uint32_t)(row*AST + seg)*2,
                  Kg + (size_t)(mm0+row)*128 + seg);
        }
    };
    auto issueV = [&](int mm0, uint32_t dst){
        #pragma unroll
        for (int it=0; it<8; it++){
            int i = tid + it*256;
            int row = i >> 4, seg = (i & 15)*8;
            cpa16(dst + (uint32_t)(row*AST + seg)*2,
                  Vg + (size_t)row*1024 + mm0 + seg);
        }
    };

    // prologue: Q + K0 + V0
    #pragma unroll
    for (int it=0; it<8; it++){
        int i = tid + it*256;
        int row = i >> 4, seg = (i & 15)*8;
        cpa16(sQa + (uint32_t)(row*AST + seg)*2, Qg + (size_t)row*128 + seg);
    }
    issueK(0);
    issueV(0, sV0a);
    CP_COMMIT();
    CP_WAIT0();
    __syncthreads();

    const uint32_t aQ  = sQa + ((qrow + (lane&15))*AST + (lane>>4)*8)*2;
    const uint32_t aPh = smem_u32(sPh) + ((qrow + (lane&15))*AST + (lane>>4)*8)*2;
    const uint32_t aPl = smem_u32(sPl) + ((qrow + (lane&15))*AST + (lane>>4)*8)*2;
    const uint32_t bK  = sKa + (((lane&7))*AST + ((lane>>3)&1)*8)*2;
    const uint32_t bVoff = (((lane&7))*AST + ((lane>>3)&1)*8)*2;

    float m0r = -1e30f, m1r = -1e30f, l0r = 0.f, l1r = 0.f;
    float o[8][4];
    #pragma unroll
    for (int i=0;i<8;i++){ o[i][0]=0.f; o[i][1]=0.f; o[i][2]=0.f; o[i][3]=0.f; }

    const int r0 = qrow + (lane>>2);
    const int pcol = (lane&3)*2;

    for (int t = 0; t < 8; t++){
        // ---- S = Q K^T (3-term) ----
        float s[16][4];
        #pragma unroll
        for (int i=0;i<16;i++){ s[i][0]=0.f; s[i][1]=0.f; s[i][2]=0.f; s[i][3]=0.f; }

        #pragma unroll
        for (int k16=0; k16<4; k16++){
            const uint32_t kb = k16*32;
            uint32_t qh[4], ql[4];
            ldmx4(qh, aQ + kb);
            ldmx4(ql, aQ + 128 + kb);
            #pragma unroll
            for (int nt=0; nt<16; nt++){
                uint32_t kh[2], kl[2];
                ldmx2(kh, bK + nt*(8*AST*2) + kb);
                ldmx2(kl, bK + nt*(8*AST*2) + 128 + kb);
                mma16816(s[nt], qh, kh);
                mma16816(s[nt], qh, kl);
                mma16816(s[nt], ql, kh);
            }
        }
        __syncthreads();                      // all warps done reading sK
        if (t < 7){                           // prefetch K(t+1), V(t+1) overlapped
            issueK((t+1)*128);
            issueV((t+1)*128, (t&1) ? sV0a : sV1a);
            CP_COMMIT();
        }

        // ---- online softmax (warp-local rows) ----
        {
            float mx = -1e30f;
            #pragma unroll
            for (int nt=0; nt<16; nt++) mx = fmaxf(mx, fmaxf(s[nt][0], s[nt][1]));
            mx = fmaxf(mx, __shfl_xor_sync(0xffffffffu, mx, 1));
            mx = fmaxf(mx, __shfl_xor_sync(0xffffffffu, mx, 2));
            float mn = fmaxf(m0r, mx);
            float corr = __expf(m0r - mn);
            m0r = mn;
            float sum = 0.f;
            #pragma unroll
            for (int nt=0; nt<16; nt++){
                float p0 = __expf(s[nt][0]-mn), p1 = __expf(s[nt][1]-mn);
                sum += p0+p1;
                __nv_bfloat162 hv = __floats2bfloat162_rn(p0, p1);
                __nv_bfloat162 lv = __floats2bfloat162_rn(
                    p0 - __bfloat162float(hv.x), p1 - __bfloat162float(hv.y));
                *(__nv_bfloat162*)&sPh[r0*AST + nt*8 + pcol] = hv;
                *(__nv_bfloat162*)&sPl[r0*AST + nt*8 + pcol] = lv;
            }
            sum += __shfl_xor_sync(0xffffffffu, sum, 1);
            sum += __shfl_xor_sync(0xffffffffu, sum, 2);
            l0r = l0r*corr + sum;
            #pragma unroll
            for (int i=0;i<8;i++){ o[i][0]*=corr; o[i][1]*=corr; }
        }
        {
            float mx = -1e30f;
            #pragma unroll
            for (int nt=0; nt<16; nt++) mx = fmaxf(mx, fmaxf(s[nt][2], s[nt][3]));
            mx = fmaxf(mx, __shfl_xor_sync(0xffffffffu, mx, 1));
            mx = fmaxf(mx, __shfl_xor_sync(0xffffffffu, mx, 2));
            float mn = fmaxf(m1r, mx);
            float corr = __expf(m1r - mn);
            m1r = mn;
            float sum = 0.f;
            #pragma unroll
            for (int nt=0; nt<16; nt++){
                float p0 = __expf(s[nt][2]-mn), p1 = __expf(s[nt][3]-mn);
                sum += p0+p1;
                __nv_bfloat162 hv = __floats2bfloat162_rn(p0, p1);
                __nv_bfloat162 lv = __floats2bfloat162_rn(
                    p0 - __bfloat162float(hv.x), p1 - __bfloat162float(hv.y));
                *(__nv_bfloat162*)&sPh[(r0+8)*AST + nt*8 + pcol] = hv;
                *(__nv_bfloat162*)&sPl[(r0+8)*AST + nt*8 + pcol] = lv;
            }
            sum += __shfl_xor_sync(0xffffffffu, sum, 1);
            sum += __shfl_xor_sync(0xffffffffu, sum, 2);
            l1r = l1r*corr + sum;
            #pragma unroll
            for (int i=0;i<8;i++){ o[i][2]*=corr; o[i][3]*=corr; }
        }
        __syncwarp();                         // P rows are warp-private

        // ---- O += P V^T (3-term); V(t) in buffer t&1 ----
        const uint32_t bV = ((t&1) ? sV1a : sV0a) + bVoff;
        #pragma unroll
        for (int k16=0; k16<8; k16++){
            const uint32_t kb = k16*32;
            uint32_t ph[4], pl[4];
            ldmx4(ph, aPh + kb);
            ldmx4(pl, aPl + kb);
            #pragma unroll
            for (int nt=0; nt<8; nt++){
                uint32_t vh[2], vl[2];
                ldmx2(vh, bV + nt*(8*AST*2) + kb);
                ldmx2(vl, bV + nt*(8*AST*2) + 64*AST*2 + kb);
                mma16816(o[nt], ph, vh);
                mma16816(o[nt], ph, vl);
                mma16816(o[nt], pl, vh);
            }
        }
        if (t < 7) CP_WAIT0();                // K(t+1), V(t+1) arrived
        __syncthreads();
    }

    // ---- normalize, stage O[q][d] in smem (reuse sPh), write ----
    float inv0 = 1.f/l0r, inv1 = 1.f/l1r;
    float* Os = (float*)sPh;
    #pragma unroll
    for (int nt=0; nt<8; nt++){
        *(float2*)&Os[r0*68 + nt*8 + pcol] =
            make_float2(o[nt][0]*inv0, o[nt][1]*inv0);
        *(float2*)&Os[(r0+8)*68 + nt*8 + pcol] =
            make_float2(o[nt][2]*inv1, o[nt][3]*inv1);
    }
    __syncthreads();

    float* op = g_att + ((size_t)(bh>>3)*NC + (size_t)(bh&7)*HD)*NHW;
    const int d = tid >> 2, l4 = tid & 3;
    #pragma unroll
    for (int j=0; j<8; j++){
        int q = l4*4 + j*16;
        float4 v;
        v.x = Os[(q+0)*68 + d];
        v.y = Os[(q+1)*68 + d];
        v.z = Os[(q+2)*68 + d];
        v.w = Os[(q+3)*68 + d];
        *(float4*)(op + (size_t)d*NHW + q0 + q) = v;
    }
}

// ============================================================================
extern "C" void kernel_launch(void* const* d_in, const int* in_sizes, int n_in,
                              void* d_out, int out_size)
{
    const float* x      = (const float*)d_in[0];
    const float* gn_w   = (const float*)d_in[1];
    const float* gn_b   = (const float*)d_in[2];
    const float* qkv_w  = (const float*)d_in[3];
    const float* qkv_b  = (const float*)d_in[4];
    const float* proj_w = (const float*)d_in[5];
    const float* proj_b = (const float*)d_in[6];
    float* out = (float*)d_out;

    float* xn;  cudaGetSymbolAddress((void**)&xn,  g_xn);
    float* att; cudaGetSymbolAddress((void**)&att, g_att);
    float* qkv; cudaGetSymbolAddress((void**)&qkv, g_qkv);
    __nv_bfloat16 *wA, *wP, *xT, *aT, *vc;
    cudaGetSymbolAddress((void**)&wA, g_wA);
    cudaGetSymbolAddress((void**)&wP, g_wP);
    cudaGetSymbolAddress((void**)&xT, g_xT);
    cudaGetSymbolAddress((void**)&aT, g_aT);
    cudaGetSymbolAddress((void**)&vc, g_vc);

    static int attr_set = 0;
    if (!attr_set){
        cudaFuncSetAttribute(attn_mma_kernel,
            cudaFuncAttributeMaxDynamicSharedMemorySize, ATT_SMEM);
        cudaFuncSetAttribute(mma_gemm_kernel,
            cudaFuncAttributeMaxDynamicSharedMemorySize, GEMM_SMEM);
        attr_set = 1;
    }

    // 1. GroupNorm -> g_xn
    gn_kernel<<<NB*NG, 256>>>(x, gn_w, gn_b);

    // 2. Convert weights + activations (hi|lo bf16, K-major)
    conv_w_kernel<<<(3*NC*NC)/1024, 256>>>(qkv_w, wA, 3*NC*NC);
    conv_w_kernel<<<(NC*NC)/1024, 256>>>(proj_w, wP, NC*NC);
    conv_actT_kernel<<<dim3(32, 16, NB), dim3(32,8)>>>(xn, xT);

    // 3. QKV GEMM (HMMA, pipelined) -> g_qkv
    mma_gemm_kernel<<<dim3(8, 12, NB), 256, GEMM_SMEM>>>(wA, xT, qkv_b,
                                                         nullptr, qkv, 3*NC);

    // 4. Convert Q (scaled, ->xT) + K (->aT) in one launch; V (->vc)
    conv_qkT_kernel<<<dim3(32, 2, 2*NB*NH), dim3(32,8)>>>(qkv, xT, aT);
    conv_v_kernel<<<dim3(64, NB*NH), 256>>>(qkv, vc);

    // 5. HMMA flash attention (pipelined) -> g_att
    attn_mma_kernel<<<dim3(8, NB*NH), 256, ATT_SMEM>>>(xT, aT, vc);

    // 6. Convert attention output (->aT), proj GEMM + residual
    conv_actT_kernel<<<dim3(32, 16, NB), dim3(32,8)>>>(att, aT);
    mma_gemm_kernel<<<dim3(8, 4, NB), 256, GEMM_SMEM>>>(wP, aT, proj_b,
                                                        x, out, NC);
}

// round 11
// speedup vs baseline: 1.0159x; 1.0159x over previous
#include <cuda_runtime.h>
#include <cuda_bf16.h>
#include <cstdint>

#define NB   8
#define NC   512
#define NHW  1024
#define NH   8
#define HD   64
#define NG   32
#define CPG  16

// -------- scratch (static device arrays; no cudaMalloc allowed) --------
__device__ float g_qkv[NB*3*NC*NHW];            // 48 MB  qkv activations (fp32)
__device__ float g_att[NB*NC*NHW];              // 16 MB  attn out as bf16 hi|lo planes
__device__ float g_mu[NB*NG], g_rs[NB*NG];      // groupnorm stats
__device__ __nv_bfloat16 g_wA[3*NC*2*NC];       //  3 MB  qkv_w  hi|lo  [1536][1024]
__device__ __nv_bfloat16 g_wP[NC*2*NC];         //  1 MB  proj_w hi|lo  [512][1024]
__device__ __nv_bfloat16 g_xT[NB*NHW*2*NC];     // 16 MB  xn^T hi|lo / QT [bh][1024][128]
__device__ __nv_bfloat16 g_aT[NB*NHW*2*NC];     // 16 MB  KT [bh][1024][128]
__device__ __nv_bfloat16 g_vc[NB*NH*2*HD*NHW];  // 16 MB  V hi|lo planes [bh][128][1024]

// -------- mma.sync / cp.async helpers --------
__device__ __forceinline__ uint32_t smem_u32(const void* p){
    uint32_t a;
    asm("{ .reg .u64 t; cvta.to.shared.u64 t, %1; cvt.u32.u64 %0, t; }"
        : "=r"(a) : "l"(p));
    return a;
}
__device__ __forceinline__ void ldmx4(uint32_t* r, uint32_t addr){
    asm volatile("ldmatrix.sync.aligned.m8n8.x4.shared.b16 {%0,%1,%2,%3}, [%4];"
        : "=r"(r[0]),"=r"(r[1]),"=r"(r[2]),"=r"(r[3]) : "r"(addr));
}
__device__ __forceinline__ void mma16816(float* d, const uint32_t* a, const uint32_t* b){
    asm volatile("mma.sync.aligned.m16n8k16.row.col.f32.bf16.bf16.f32 "
        "{%0,%1,%2,%3}, {%4,%5,%6,%7}, {%8,%9}, {%0,%1,%2,%3};"
        : "+f"(d[0]),"+f"(d[1]),"+f"(d[2]),"+f"(d[3])
        : "r"(a[0]),"r"(a[1]),"r"(a[2]),"r"(a[3]), "r"(b[0]),"r"(b[1]));
}
__device__ __forceinline__ void cpa16(uint32_t s, const void* g){
    asm volatile("cp.async.cg.shared.global [%0], [%1], 16;" :: "r"(s), "l"(g));
}
#define CP_COMMIT() asm volatile("cp.async.commit_group;" ::: "memory")
#define CP_WAIT0()  asm volatile("cp.async.wait_group 0;" ::: "memory")

// ============================================================================
// GroupNorm stats only: one block per (b,g); writes mu, rstd
// ============================================================================
__global__ void __launch_bounds__(256)
gn_stats_kernel(const float* __restrict__ x)
{
    const int GSZ4 = CPG*NHW/4;
    int bg = blockIdx.x;
    const float4* xp = (const float4*)(x + (size_t)bg*CPG*NHW);

    float s = 0.f, s2 = 0.f;
    for (int i = threadIdx.x; i < GSZ4; i += 256){
        float4 v = xp[i];
        s  += (v.x+v.y)+(v.z+v.w);
        s2 += (v.x*v.x+v.y*v.y)+(v.z*v.z+v.w*v.w);
    }
    #pragma unroll
    for (int m=16;m;m>>=1){
        s  += __shfl_xor_sync(0xffffffffu, s,  m);
        s2 += __shfl_xor_sync(0xffffffffu, s2, m);
    }
    __shared__ float shA[8], shB[8];
    int w = threadIdx.x>>5, l = threadIdx.x&31;
    if (l==0){ shA[w]=s; shB[w]=s2; }
    __syncthreads();
    if (threadIdx.x==0){
        float S=0.f, S2=0.f;
        #pragma unroll
        for (int i=0;i<8;i++){ S+=shA[i]; S2+=shB[i]; }
        const float inv = 1.f/(float)(CPG*NHW);
        float mu  = S*inv;
        float var = S2*inv - mu*mu;
        g_mu[bg] = mu;
        g_rs[bg] = rsqrtf(var + 1e-5f);
    }
}

// ============================================================================
// Weight converter: fp32 [M][512] -> bf16 hi|lo [M][1024]
// ============================================================================
__global__ void __launch_bounds__(256)
conv_w_kernel(const float* __restrict__ w, __nv_bfloat16* __restrict__ o, int total)
{
    int i = (blockIdx.x*256 + threadIdx.x)*4;
    if (i >= total) return;
    float4 v = *(const float4*)(w + i);
    int m = i >> 9, k = i & 511;
    __nv_bfloat16* row = o + (size_t)m*1024;
    float a[4] = {v.x, v.y, v.z, v.w};
    #pragma unroll
    for (int j=0;j<4;j++){
        __nv_bfloat16 h = __float2bfloat16(a[j]);
        row[k+j]       = h;
        row[512+k+j]   = __float2bfloat16(a[j] - __bfloat162float(h));
    }
}

// ============================================================================
// Fused GroupNorm-apply + transpose-converter:
// x [z][512 k][1024 n] -> bf16 hi|lo [z][1024 n][1024 (k|k+512)]
// ============================================================================
__global__ void __launch_bounds__(256)
conv_xnT_kernel(const float* __restrict__ x,
                const float* __restrict__ gw,
                const float* __restrict__ gb,
                __nv_bfloat16* __restrict__ out)
{
    __shared__ float t[32][33];
    int n0 = blockIdx.x*32, k0 = blockIdx.y*32, z = blockIdx.z;
    int tx = threadIdx.x, ty = threadIdx.y;
    const float* ip = x + ((size_t)z*NC + k0)*NHW + n0;
    #pragma unroll
    for (int j=0;j<4;j++)
        t[ty*4+j][tx] = ip[(size_t)(ty*4+j)*NHW + tx];
    __syncthreads();
    const int c = k0 + tx;
    const int g = c >> 4;                      // CPG = 16
    float mu = g_mu[z*NG+g], rs = g_rs[z*NG+g];
    float a = gw[c]*rs, off = gb[c] - mu*a;
    __nv_bfloat16* op = out + ((size_t)z*NHW + n0)*1024 + k0;
    #pragma unroll
    for (int j=0;j<4;j++){
        int nl = ty*4+j;
        float v = t[tx][nl]*a + off;
        __nv_bfloat16 h = __float2bfloat16(v);
        op[(size_t)nl*1024 + tx]       = h;
        op[(size_t)nl*1024 + 512 + tx] = __float2bfloat16(v - __bfloat162float(h));
    }
}

// ============================================================================
// Q+K transpose-converter (merged): z<64 -> Q (scale 1/8), z>=64 -> K
// out [bh][n 1024][d-hi 64|d-lo 64]
// ============================================================================
__global__ void __launch_bounds__(256)
conv_qkT_kernel(const float* __restrict__ in,
                __nv_bfloat16* __restrict__ outQ,
                __nv_bfloat16* __restrict__ outK)
{
    __shared__ float t[32][33];
    int zz = blockIdx.z;
    int isK = zz >= NB*NH;
    int bh = zz & 63;
    int b = bh >> 3, h = bh & 7;
    int coff  = isK ? NC : 0;
    float scale = isK ? 1.0f : 0.125f;
    __nv_bfloat16* out = isK ? outK : outQ;

    int n0 = blockIdx.x*32, d0 = blockIdx.y*32;
    int tx = threadIdx.x, ty = threadIdx.y;
    const float* ip = in + ((size_t)b*3*NC + coff + h*HD + d0)*NHW + n0;
    #pragma unroll
    for (int j=0;j<4;j++)
        t[ty*4+j][tx] = ip[(size_t)(ty*4+j)*NHW + tx];
    __syncthreads();
    __nv_bfloat16* op = out + ((size_t)bh*NHW + n0)*128 + d0;
    #pragma unroll
    for (int j=0;j<4;j++){
        int nl = ty*4+j;
        float v = t[tx][nl]*scale;
        __nv_bfloat16 hv = __float2bfloat16(v);
        op[(size_t)nl*128 + tx]      = hv;
        op[(size_t)nl*128 + 64 + tx] = __float2bfloat16(v - __bfloat162float(hv));
    }
}

// ============================================================================
// V converter: g_qkv V part -> g_vc [bh][d|d+64][m] hi|lo planes
// ============================================================================
__global__ void __launch_bounds__(256)
conv_v_kernel(const float* __restrict__ in, __nv_bfloat16* __restrict__ out)
{
    int bh = blockIdx.y, b = bh >> 3, h = bh & 7;
    int idx = (blockIdx.x*256 + threadIdx.x)*4;
    int d = idx >> 10, m = idx & 1023;
    float4 v = *(const float4*)(in + ((size_t)b*3*NC + 2*NC + h*HD + d)*NHW + m);
    __nv_bfloat16* o = out + (size_t)bh*128*1024;
    float a[4] = {v.x, v.y, v.z, v.w};
    __nv_bfloat16 hi[4], lo[4];
    #pragma unroll
    for (int j=0;j<4;j++){
        hi[j] = __float2bfloat16(a[j]);
        lo[j] = __float2bfloat16(a[j] - __bfloat162float(hi[j]));
    }
    *(uint2*)(o + (size_t)d*1024 + m)        = *(uint2*)hi;
    *(uint2*)(o + (size_t)(d+64)*1024 + m)   = *(uint2*)lo;
}

// ============================================================================
// HMMA split GEMM, 2-stage cp.async pipeline + paired-x4 B loads.
// ============================================================================
#define TPAD   72
#define TILE_E (128*TPAD)
#define STAGE_B (4*TILE_E*2)
#define GEMM_SMEM (2*STAGE_B)           // 147456

__global__ void __launch_bounds__(256,1)
mma_gemm_kernel(const __nv_bfloat16* __restrict__ A2,
                const __nv_bfloat16* __restrict__ B2t,
                const float* __restrict__ bias,
                const float* __restrict__ res,
                float* __restrict__ C,
                int M)
{
    extern __shared__ __nv_bfloat16 sm[];
    const int tid  = threadIdx.x;
    const int warp = tid >> 5, lane = tid & 31;
    const int wm = warp >> 2, wn = warp & 3;
    const int n0 = blockIdx.x*128, m0 = blockIdx.y*128, z = blockIdx.z;

    const __nv_bfloat16* Ag = A2 + (size_t)m0*1024;
    const __nv_bfloat16* Bg = B2t + ((size_t)z*NHW + n0)*1024;

    const uint32_t smBase = smem_u32(sm);
    const int aOff = (wm*64 + (lane & 15))*TPAD + (lane >> 4)*8;
    // paired-x4 B: lanes 0-7 row+0/col+0, 8-15 row+0/col+8, 16-23 row+8/col+0, 24-31 row+8/col+8
    const int bOff = (wn*32 + (lane & 7) + ((lane >> 4) & 1)*8)*TPAD + ((lane >> 3) & 1)*8;
    const uint32_t fA = smBase + aOff*2;
    const uint32_t fB = smBase + bOff*2;

    const int crow = tid >> 3, cseg = (tid & 7)*8;

    auto issue_chunk = [&](int c){
        const int st = c & 1;
        const uint32_t base = smBase + st*STAGE_B;
        const int kh = c*64, kl = 512 + c*64;
        #pragma unroll
        for (int it=0; it<4; it++){
            int row = crow + it*32;
            uint32_t so = (uint32_t)(row*TPAD + cseg)*2;
            size_t go = (size_t)row*1024 + cseg;
            cpa16(base +              so, Ag + go + kh);
            cpa16(base + TILE_E*2   + so, Ag + go + kl);
            cpa16(base + 2*TILE_E*2 + so, Bg + go + kh);
            cpa16(base + 3*TILE_E*2 + so, Bg + go + kl);
        }
        CP_COMMIT();
    };

    float acc[4][4][4];
    #pragma unroll
    for (int i=0;i<4;i++)
        #pragma unroll
        for (int j=0;j<4;j++)
            #pragma unroll
            for (int r=0;r<4;r++) acc[i][j][r]=0.f;

    issue_chunk(0);

    for (int c = 0; c < 8; c++){
        CP_WAIT0();
        __syncthreads();
        if (c < 7) issue_chunk(c+1);

        const uint32_t so = (c & 1)*STAGE_B;
        const uint32_t sAhA = fA + so,              sAlA = fA + so + TILE_E*2;
        const uint32_t sBhA = fB + so + 2*TILE_E*2, sBlA = fB + so + 3*TILE_E*2;

        #pragma unroll
        for (int k16 = 0; k16 < 4; k16++){
            const uint32_t kb = k16*32;
            uint32_t bh4[2][4], bl4[2][4];
            #pragma unroll
            for (int p=0; p<2; p++){
                ldmx4(bh4[p], sBhA + p*(16*TPAD*2) + kb);
                ldmx4(bl4[p], sBlA + p*(16*TPAD*2) + kb);
            }
            #pragma unroll
            for (int mt=0; mt<4; mt++){
                uint32_t ah[4], al[4];
                ldmx4(ah, sAhA + mt*(16*TPAD*2) + kb);
                ldmx4(al, sAlA + mt*(16*TPAD*2) + kb);
                #pragma unroll
                for (int p=0; p<2; p++){
                    mma16816(acc[mt][2*p],   ah, &bh4[p][0]);
                    mma16816(acc[mt][2*p],   ah, &bl4[p][0]);
                    mma16816(acc[mt][2*p],   al, &bh4[p][0]);
                    mma16816(acc[mt][2*p+1], ah, &bh4[p][2]);
                    mma16816(acc[mt][2*p+1], ah, &bl4[p][2]);
                    mma16816(acc[mt][2*p+1], al, &bh4[p][2]);
                }
            }
        }
    }

    const int rBase = m0 + wm*64 + (lane >> 2);
    const int cBase = n0 + wn*32 + (lane & 3)*2;
    #pragma unroll
    for (int mt=0; mt<4; mt++){
        const int r0 = rBase + mt*16;
        const float bi0 = bias[r0], bi1 = bias[r0+8];
        float* cp0 = C + ((size_t)z*M + r0  )*NHW;
        float* cp1 = C + ((size_t)z*M + r0+8)*NHW;
        const float* rp0 = res ? res + ((size_t)z*M + r0  )*NHW : nullptr;
        const float* rp1 = res ? res + ((size_t)z*M + r0+8)*NHW : nullptr;
        #pragma unroll
        for (int nt=0; nt<4; nt++){
            const int cc = cBase + nt*8;
            float2 v0 = make_float2(acc[mt][nt][0]+bi0, acc[mt][nt][1]+bi0);
            float2 v1 = make_float2(acc[mt][nt][2]+bi1, acc[mt][nt][3]+bi1);
            if (rp0){
                float2 a0 = *(const float2*)(rp0 + cc);
                float2 a1 = *(const float2*)(rp1 + cc);
                v0.x+=a0.x; v0.y+=a0.y; v1.x+=a1.x; v1.y+=a1.y;
            }
            *(float2*)(cp0 + cc) = v0;
            *(float2*)(cp1 + cc) = v1;
        }
    }
}

// ============================================================================
// HMMA flash attention: cp.async overlap, double-buffered V, paired-x4 K/V
// loads, epilogue writes proj-B bf16 hi|lo layout directly.
// ============================================================================
#define AST 136
#define ATE (128*AST)
#define ATT_SMEM (6*ATE*2)              // Q,K,V0,V1,Ph,Pl = 208896 B

__global__ void __launch_bounds__(256)
attn_mma_kernel(const __nv_bfloat16* __restrict__ QT,
                const __nv_bfloat16* __restrict__ KT,
                const __nv_bfloat16* __restrict__ Vc,
                __nv_bfloat16* __restrict__ OutB)
{
    extern __shared__ __nv_bfloat16 sm[];
    __nv_bfloat16* sQ  = sm;
    __nv_bfloat16* sK  = sm + ATE;
    __nv_bfloat16* sPh = sm + 4*ATE;
    __nv_bfloat16* sPl = sm + 5*ATE;
    const uint32_t sV0a = smem_u32(sm + 2*ATE);
    const uint32_t sV1a = smem_u32(sm + 3*ATE);

    const int tid = threadIdx.x, warp = tid >> 5, lane = tid & 31;
    const int q0 = blockIdx.x*128, bh = blockIdx.y;
    const int qrow = warp*16;

    const __nv_bfloat16* Qg = QT + ((size_t)bh*NHW + q0)*128;
    const __nv_bfloat16* Kg = KT + (size_t)bh*NHW*128;
    const __nv_bfloat16* Vg = Vc + (size_t)bh*128*1024;

    const uint32_t sQa = smem_u32(sQ), sKa = smem_u32(sK);
    auto issueK = [&](int mm0){
        #pragma unroll
        for (int it=0; it<8; it++){
            int i = tid + it*256;
            int row = i >> 4, seg = (i & 15)*8;
            cpa16(sKa + (uint32_t)(row*AST + seg)*2,
                  Kg + (size_t)(mm0+row)*128 + seg);
        }
    };
    auto issueV = [&](int mm0, uint32_t dst){
        #pragma unroll
        for (int it=0; it<8; it++){
            int i = tid + it*256;
            int row = i >> 4, seg = (i & 15)*8;
            cpa16(dst + (uint32_t)(row*AST + seg)*2,
                  Vg + (size_t)row*1024 + mm0 + seg);
        }
    };

    // prologue: Q + K0 + V0
    #pragma unroll
    for (int it=0; it<8; it++){
        int i = tid + it*256;
        int row = i >> 4, seg = (i & 15)*8;
        cpa16(sQa + (uint32_t)(row*AST + seg)*2, Qg + (size_t)row*128 + seg);
    }
    issueK(0);
    issueV(0, sV0a);
    CP_COMMIT();
    CP_WAIT0();
    __syncthreads();

    const uint32_t aQ  = sQa + ((qrow + (lane&15))*AST + (lane>>4)*8)*2;
    const uint32_t aPh = smem_u32(sPh) + ((qrow + (lane&15))*AST + (lane>>4)*8)*2;
    const uint32_t aPl = smem_u32(sPl) + ((qrow + (lane&15))*AST + (lane>>4)*8)*2;
    // paired-x4 B addressing for K and V
    const uint32_t bOffP = (((lane&7) + ((lane>>4)&1)*8)*AST + ((lane>>3)&1)*8)*2;
    const uint32_t bK = sKa + bOffP;

    float m0r = -1e30f, m1r = -1e30f, l0r = 0.f, l1r = 0.f;
    float o[8][4];
    #pragma unroll
    for (int i=0;i<8;i++){ o[i][0]=0.f; o[i][1]=0.f; o[i][2]=0.f; o[i][3]=0.f; }

    const int r0 = qrow + (lane>>2);
    const int pcol = (lane&3)*2;

    for (int t = 0; t < 8; t++){
        // ---- S = Q K^T (3-term), paired-x4 K loads ----
        float s[16][4];
        #pragma unroll
        for (int i=0;i<16;i++){ s[i][0]=0.f; s[i][1]=0.f; s[i][2]=0.f; s[i][3]=0.f; }

        #pragma unroll
        for (int k16=0; k16<4; k16++){
            const uint32_t kb = k16*32;
            uint32_t qh[4], ql[4];
            ldmx4(qh, aQ + kb);
            ldmx4(ql, aQ + 128 + kb);
            #pragma unroll
            for (int p=0; p<8; p++){
                uint32_t kh4[4], kl4[4];
                ldmx4(kh4, bK + p*(16*AST*2) + kb);
                ldmx4(kl4, bK + p*(16*AST*2) + 128 + kb);
                mma16816(s[2*p],   qh, &kh4[0]);
                mma16816(s[2*p],   qh, &kl4[0]);
                mma16816(s[2*p],   ql, &kh4[0]);
                mma16816(s[2*p+1], qh, &kh4[2]);
                mma16816(s[2*p+1], qh, &kl4[2]);
                mma16816(s[2*p+1], ql, &kh4[2]);
            }
        }
        __syncthreads();                      // all warps done reading sK
        if (t < 7){
            issueK((t+1)*128);
            issueV((t+1)*128, (t&1) ? sV0a : sV1a);
            CP_COMMIT();
        }

        // ---- online softmax (warp-local rows) ----
        {
            float mx = -1e30f;
            #pragma unroll
            for (int nt=0; nt<16; nt++) mx = fmaxf(mx, fmaxf(s[nt][0], s[nt][1]));
            mx = fmaxf(mx, __shfl_xor_sync(0xffffffffu, mx, 1));
            mx = fmaxf(mx, __shfl_xor_sync(0xffffffffu, mx, 2));
            float mn = fmaxf(m0r, mx);
            float corr = __expf(m0r - mn);
            m0r = mn;
            float sum = 0.f;
            #pragma unroll
            for (int nt=0; nt<16; nt++){
                float p0 = __expf(s[nt][0]-mn), p1 = __expf(s[nt][1]-mn);
                sum += p0+p1;
                __nv_bfloat162 hv = __floats2bfloat162_rn(p0, p1);
                __nv_bfloat162 lv = __floats2bfloat162_rn(
                    p0 - __bfloat162float(hv.x), p1 - __bfloat162float(hv.y));
                *(__nv_bfloat162*)&sPh[r0*AST + nt*8 + pcol] = hv;
                *(__nv_bfloat162*)&sPl[r0*AST + nt*8 + pcol] = lv;
            }
            sum += __shfl_xor_sync(0xffffffffu, sum, 1);
            sum += __shfl_xor_sync(0xffffffffu, sum, 2);
            l0r = l0r*corr + sum;
            #pragma unroll
            for (int i=0;i<8;i++){ o[i][0]*=corr; o[i][1]*=corr; }
        }
        {
            float mx = -1e30f;
            #pragma unroll
            for (int nt=0; nt<16; nt++) mx = fmaxf(mx, fmaxf(s[nt][2], s[nt][3]));
            mx = fmaxf(mx, __shfl_xor_sync(0xffffffffu, mx, 1));
            mx = fmaxf(mx, __shfl_xor_sync(0xffffffffu, mx, 2));
            float mn = fmaxf(m1r, mx);
            float corr = __expf(m1r - mn);
            m1r = mn;
            float sum = 0.f;
            #pragma unroll
            for (int nt=0; nt<16; nt++){
                float p0 = __expf(s[nt][2]-mn), p1 = __expf(s[nt][3]-mn);
                sum += p0+p1;
                __nv_bfloat162 hv = __floats2bfloat162_rn(p0, p1);
                __nv_bfloat162 lv = __floats2bfloat162_rn(
                    p0 - __bfloat162float(hv.x), p1 - __bfloat162float(hv.y));
                *(__nv_bfloat162*)&sPh[(r0+8)*AST + nt*8 + pcol] = hv;
                *(__nv_bfloat162*)&sPl[(r0+8)*AST + nt*8 + pcol] = lv;
            }
            sum += __shfl_xor_sync(0xffffffffu, sum, 1);
            sum += __shfl_xor_sync(0xffffffffu, sum, 2);
            l1r = l1r*corr + sum;
            #pragma unroll
            for (int i=0;i<8;i++){ o[i][2]*=corr; o[i][3]*=corr; }
        }
        __syncwarp();

        // ---- O += P V^T (3-term), paired-x4 V loads ----
        const uint32_t bV = ((t&1) ? sV1a : sV0a) + bOffP;
        #pragma unroll
        for (int k16=0; k16<8; k16++){
            const uint32_t kb = k16*32;
            uint32_t ph[4], pl[4];
            ldmx4(ph, aPh + kb);
            ldmx4(pl, aPl + kb);
            #pragma unroll
            for (int p=0; p<4; p++){
                uint32_t vh4[4], vl4[4];
                ldmx4(vh4, bV + p*(16*AST*2) + kb);
                ldmx4(vl4, bV + p*(16*AST*2) + 64*AST*2 + kb);
                mma16816(o[2*p],   ph, &vh4[0]);
                mma16816(o[2*p],   ph, &vl4[0]);
                mma16816(o[2*p],   pl, &vh4[0]);
                mma16816(o[2*p+1], ph, &vh4[2]);
                mma16816(o[2*p+1], ph, &vl4[2]);
                mma16816(o[2*p+1], pl, &vh4[2]);
            }
        }
        if (t < 7) CP_WAIT0();
        __syncthreads();
    }

    // ---- normalize, stage O[q][d] in smem, write proj-B bf16 hi|lo ----
    float inv0 = 1.f/l0r, inv1 = 1.f/l1r;
    float* Os = (float*)sPh;                  // [128 q][68 f32]
    #pragma unroll
    for (int nt=0; nt<8; nt++){
        *(float2*)&Os[r0*68 + nt*8 + pcol] =
            make_float2(o[nt][0]*inv0, o[nt][1]*inv0);
        *(float2*)&Os[(r0+8)*68 + nt*8 + pcol] =
            make_float2(o[nt][2]*inv1, o[nt][3]*inv1);
    }
    __syncthreads();

    // OutB row n = q0+q, cols [h*64 + d] hi, [512 + h*64 + d] lo
    const int z = bh >> 3, h = bh & 7;
    __nv_bfloat16* ob = OutB + ((size_t)z*NHW + q0)*1024 + h*64;
    const int q = tid & 127, part = tid >> 7;   // part 0 = hi, 1 = lo
    const float* row = Os + q*68;
    __nv_bfloat16 buf[64];
    #pragma unroll
    for (int d=0; d<64; d++){
        float v = row[d];
        __nv_bfloat16 hv = __float2bfloat16(v);
        buf[d] = part ? __float2bfloat16(v - __bfloat162float(hv)) : hv;
    }
    __nv_bfloat16* dst = ob + (size_t)q*1024 + part*512;
    #pragma unroll
    for (int j=0; j<8; j++)
        *(uint4*)(dst + j*8) = *(const uint4*)(buf + j*8);
}

// ============================================================================
extern "C" void kernel_launch(void* const* d_in, const int* in_sizes, int n_in,
                              void* d_out, int out_size)
{
    const float* x      = (const float*)d_in[0];
    const float* gn_w   = (const float*)d_in[1];
    const float* gn_b   = (const float*)d_in[2];
    const float* qkv_w  = (const float*)d_in[3];
    const float* qkv_b  = (const float*)d_in[4];
    const float* proj_w = (const float*)d_in[5];
    const float* proj_b = (const float*)d_in[6];
    float* out = (float*)d_out;

    float* att; cudaGetSymbolAddress((void**)&att, g_att);
    float* qkv; cudaGetSymbolAddress((void**)&qkv, g_qkv);
    __nv_bfloat16 *wA, *wP, *xT, *aT, *vc;
    cudaGetSymbolAddress((void**)&wA, g_wA);
    cudaGetSymbolAddress((void**)&wP, g_wP);
    cudaGetSymbolAddress((void**)&xT, g_xT);
    cudaGetSymbolAddress((void**)&aT, g_aT);
    cudaGetSymbolAddress((void**)&vc, g_vc);
    __nv_bfloat16* attB = (__nv_bfloat16*)att;

    static int attr_set = 0;
    if (!attr_set){
        cudaFuncSetAttribute(attn_mma_kernel,
            cudaFuncAttributeMaxDynamicSharedMemorySize, ATT_SMEM);
        cudaFuncSetAttribute(mma_gemm_kernel,
            cudaFuncAttributeMaxDynamicSharedMemorySize, GEMM_SMEM);
        attr_set = 1;
    }

    // 1. GroupNorm stats
    gn_stats_kernel<<<NB*NG, 256>>>(x);

    // 2. Convert weights; fused gn-apply + transpose of x -> xT
    conv_w_kernel<<<(3*NC*NC)/1024, 256>>>(qkv_w, wA, 3*NC*NC);
    conv_w_kernel<<<(NC*NC)/1024, 256>>>(proj_w, wP, NC*NC);
    conv_xnT_kernel<<<dim3(32, 16, NB), dim3(32,8)>>>(x, gn_w, gn_b, xT);

    // 3. QKV GEMM (HMMA, pipelined) -> g_qkv
    mma_gemm_kernel<<<dim3(8, 12, NB), 256, GEMM_SMEM>>>(wA, xT, qkv_b,
                                                         nullptr, qkv, 3*NC);

    // 4. Convert Q (scaled, ->xT) + K (->aT); V (->vc)
    conv_qkT_kernel<<<dim3(32, 2, 2*NB*NH), dim3(32,8)>>>(qkv, xT, aT);
    conv_v_kernel<<<dim3(64, NB*NH), 256>>>(qkv, vc);

    // 5. HMMA flash attention -> attB (proj-B layout, bf16 hi|lo)
    attn_mma_kernel<<<dim3(8, NB*NH), 256, ATT_SMEM>>>(xT, aT, vc, attB);

    // 6. proj GEMM + residual -> out
    mma_gemm_kernel<<<dim3(8, 4, NB), 256, GEMM_SMEM>>>(wP, attB, proj_b,
                                                        x, out, NC);
}

// round 12
// speedup vs baseline: 1.1969x; 1.1781x over previous
#include <cuda_runtime.h>
#include <cuda_bf16.h>
#include <cstdint>

#define NB   8
#define NC   512
#define NHW  1024
#define NH   8
#define HD   64
#define NG   32
#define CPG  16

// -------- scratch (static device arrays; no cudaMalloc allowed) --------
__device__ float g_qkv [NB*3*NC*NHW];           // 48 MB qkv activations fp32
__device__ float g_attB[NB*NHW*NC];             // 16 MB attn out, proj-B layout [z][n][512]
__device__ float g_mu[NB*NG], g_rs[NB*NG];      // groupnorm stats
__device__ float g_wAf[3*NC*NC];                //  3 MB qkv_w rna-tf32 [1536][512]
__device__ float g_wPf[NC*NC];                  //  1 MB proj_w rna-tf32 [512][512]
__device__ float g_xnT[NB*NHW*NC];              // 16 MB xn^T [z][1024][512]
__device__ float g_QT [NB*NH*NHW*HD];           // 16 MB Q^T/8 [bh][1024][64]
__device__ float g_KT [NB*NH*NHW*HD];           // 16 MB K^T   [bh][1024][64]

// -------- helpers --------
__device__ __forceinline__ uint32_t smem_u32(const void* p){
    uint32_t a;
    asm("{ .reg .u64 t; cvta.to.shared.u64 t, %1; cvt.u32.u64 %0, t; }"
        : "=r"(a) : "l"(p));
    return a;
}
__device__ __forceinline__ void ldmx4(uint32_t* r, uint32_t addr){
    asm volatile("ldmatrix.sync.aligned.m8n8.x4.shared.b16 {%0,%1,%2,%3}, [%4];"
        : "=r"(r[0]),"=r"(r[1]),"=r"(r[2]),"=r"(r[3]) : "r"(addr));
}
__device__ __forceinline__ void mma1688(float* d, const uint32_t* a, const uint32_t* b){
    asm volatile("mma.sync.aligned.m16n8k8.row.col.f32.tf32.tf32.f32 "
        "{%0,%1,%2,%3}, {%4,%5,%6,%7}, {%8,%9}, {%0,%1,%2,%3};"
        : "+f"(d[0]),"+f"(d[1]),"+f"(d[2]),"+f"(d[3])
        : "r"(a[0]),"r"(a[1]),"r"(a[2]),"r"(a[3]), "r"(b[0]),"r"(b[1]));
}
__device__ __forceinline__ float rtf(float x){
    uint32_t y; asm("cvt.rna.tf32.f32 %0, %1;" : "=r"(y) : "f"(x));
    return __uint_as_float(y);
}
__device__ __forceinline__ void cpa16(uint32_t s, const void* g){
    asm volatile("cp.async.cg.shared.global [%0], [%1], 16;" :: "r"(s), "l"(g));
}
#define CP_COMMIT() asm volatile("cp.async.commit_group;" ::: "memory")
#define CP_WAIT0()  asm volatile("cp.async.wait_group 0;" ::: "memory")

// ============================================================================
// GroupNorm stats (validated)
// ============================================================================
__global__ void __launch_bounds__(256)
gn_stats_kernel(const float* __restrict__ x)
{
    const int GSZ4 = CPG*NHW/4;
    int bg = blockIdx.x;
    const float4* xp = (const float4*)(x + (size_t)bg*CPG*NHW);

    float s = 0.f, s2 = 0.f;
    for (int i = threadIdx.x; i < GSZ4; i += 256){
        float4 v = xp[i];
        s  += (v.x+v.y)+(v.z+v.w);
        s2 += (v.x*v.x+v.y*v.y)+(v.z*v.z+v.w*v.w);
    }
    #pragma unroll
    for (int m=16;m;m>>=1){
        s  += __shfl_xor_sync(0xffffffffu, s,  m);
        s2 += __shfl_xor_sync(0xffffffffu, s2, m);
    }
    __shared__ float shA[8], shB[8];
    int w = threadIdx.x>>5, l = threadIdx.x&31;
    if (l==0){ shA[w]=s; shB[w]=s2; }
    __syncthreads();
    if (threadIdx.x==0){
        float S=0.f, S2=0.f;
        #pragma unroll
        for (int i=0;i<8;i++){ S+=shA[i]; S2+=shB[i]; }
        const float inv = 1.f/(float)(CPG*NHW);
        float mu  = S*inv;
        float var = S2*inv - mu*mu;
        g_mu[bg] = mu;
        g_rs[bg] = rsqrtf(var + 1e-5f);
    }
}

// ============================================================================
// Weight converter: rna-round fp32 to tf32 bit-pattern (elementwise)
// ============================================================================
__global__ void __launch_bounds__(256)
conv_w_kernel(const float* __restrict__ w, float* __restrict__ o, int total)
{
    int i = (blockIdx.x*256 + threadIdx.x)*4;
    if (i >= total) return;
    float4 v = *(const float4*)(w + i);
    float4 r = make_float4(rtf(v.x), rtf(v.y), rtf(v.z), rtf(v.w));
    *(float4*)(o + i) = r;
}

// ============================================================================
// Fused GroupNorm-apply + transpose: x [z][512][1024] -> [z][1024 n][512 k] tf32
// ============================================================================
__global__ void __launch_bounds__(256)
conv_xnT_kernel(const float* __restrict__ x,
                const float* __restrict__ gw,
                const float* __restrict__ gb,
                float* __restrict__ out)
{
    __shared__ float t[32][33];
    int n0 = blockIdx.x*32, k0 = blockIdx.y*32, z = blockIdx.z;
    int tx = threadIdx.x, ty = threadIdx.y;
    const float* ip = x + ((size_t)z*NC + k0)*NHW + n0;
    #pragma unroll
    for (int j=0;j<4;j++)
        t[ty*4+j][tx] = ip[(size_t)(ty*4+j)*NHW + tx];
    __syncthreads();
    const int c = k0 + tx;
    const int g = c >> 4;
    float mu = g_mu[z*NG+g], rs = g_rs[z*NG+g];
    float a = gw[c]*rs, off = gb[c] - mu*a;
    float* op = out + ((size_t)z*NHW + n0)*NC + k0;
    #pragma unroll
    for (int j=0;j<4;j++){
        int nl = ty*4+j;
        op[(size_t)nl*NC + tx] = rtf(t[tx][nl]*a + off);
    }
}

// ============================================================================
// Q+K transpose: z<64 -> Q (scale 1/8), z>=64 -> K. out [bh][1024 n][64 d] tf32
// ============================================================================
__global__ void __launch_bounds__(256)
conv_qkT_kernel(const float* __restrict__ in,
                float* __restrict__ outQ,
                float* __restrict__ outK)
{
    __shared__ float t[32][33];
    int zz = blockIdx.z;
    int isK = zz >= NB*NH;
    int bh = zz & 63;
    int b = bh >> 3, h = bh & 7;
    int coff  = isK ? NC : 0;
    float scale = isK ? 1.0f : 0.125f;
    float* out = isK ? outK : outQ;

    int n0 = blockIdx.x*32, d0 = blockIdx.y*32;
    int tx = threadIdx.x, ty = threadIdx.y;
    const float* ip = in + ((size_t)b*3*NC + coff + h*HD + d0)*NHW + n0;
    #pragma unroll
    for (int j=0;j<4;j++)
        t[ty*4+j][tx] = ip[(size_t)(ty*4+j)*NHW + tx];
    __syncthreads();
    float* op = out + ((size_t)bh*NHW + n0)*HD + d0;
    #pragma unroll
    for (int j=0;j<4;j++){
        int nl = ty*4+j;
        op[(size_t)nl*HD + tx] = rtf(t[tx][nl]*scale);
    }
}

// ============================================================================
// TF32 GEMM: C[z][m][n] = A[m][:512] * B[z][n][:512]^T + bias[m] (+ res)
// 128x128 tile, K-chunks of 64, 2-stage cp.async, 8 warps = 2m x 4n.
// ============================================================================
#define GST 68                          // floats per smem row (272 B, odd*16B)
#define GTE (128*GST)                   // floats per tile
#define GSTAGE (2*GTE)                  // A+B floats per stage
#define GEMM_SMEM (2*GSTAGE*4)          // 139264 B

__global__ void __launch_bounds__(256,1)
mma_gemm_kernel(const float* __restrict__ A2,
                const float* __restrict__ B2t,
                const float* __restrict__ bias,
                const float* __restrict__ res,
                float* __restrict__ C,
                int M)
{
    extern __shared__ float smf[];
    const int tid  = threadIdx.x;
    const int warp = tid >> 5, lane = tid & 31;
    const int wm = warp >> 2, wn = warp & 3;
    const int n0 = blockIdx.x*128, m0 = blockIdx.y*128, z = blockIdx.z;

    const float* Ag = A2 + (size_t)m0*NC;
    const float* Bg = B2t + ((size_t)z*NHW + n0)*NC;

    const uint32_t smBase = smem_u32(smf);
    // A frag: bit3 of lane -> row+8, bit4 -> col+4 (tf32 view of b16 ldmatrix)
    const int rowA = (lane&7) + ((lane>>3)&1)*8;
    const int colA = ((lane>>4)&1)*4;
    // B frag (paired two n-tiles): bit4 -> row+8, bit3 -> col+4
    const int rowB = (lane&7) + ((lane>>4)&1)*8;
    const int colB = ((lane>>3)&1)*4;
    const uint32_t aBase = smBase + ((wm*64 + rowA)*GST + colA)*4;
    const uint32_t bBase = smBase + GTE*4 + ((wn*32 + rowB)*GST + colB)*4;

    auto issue_chunk = [&](int c){
        const uint32_t base = smBase + (c & 1)*GSTAGE*4;
        const int kh = c*64;
        #pragma unroll
        for (int it=0; it<8; it++){
            int i = tid + it*256;
            int row = i >> 4, seg = (i & 15)*4;
            cpa16(base + (uint32_t)(row*GST + seg)*4,
                  Ag + (size_t)row*NC + kh + seg);
            cpa16(base + GTE*4 + (uint32_t)(row*GST + seg)*4,
                  Bg + (size_t)row*NC + kh + seg);
        }
        CP_COMMIT();
    };

    float acc[4][4][4];
    #pragma unroll
    for (int i=0;i<4;i++)
        #pragma unroll
        for (int j=0;j<4;j++)
            #pragma unroll
            for (int r=0;r<4;r++) acc[i][j][r]=0.f;

    issue_chunk(0);

    for (int c = 0; c < 8; c++){
        CP_WAIT0();
        __syncthreads();
        if (c < 7) issue_chunk(c+1);

        const uint32_t so = (c & 1)*GSTAGE*4;
        #pragma unroll
        for (int k8 = 0; k8 < 8; k8++){
            const uint32_t kb = k8*32;
            uint32_t b4[2][4];
            ldmx4(b4[0], bBase + so + kb);
            ldmx4(b4[1], bBase + so + 16*GST*4 + kb);
            #pragma unroll
            for (int mt=0; mt<4; mt++){
                uint32_t a4[4];
                ldmx4(a4, aBase + so + mt*(16*GST*4) + kb);
                mma1688(acc[mt][0], a4, &b4[0][0]);
                mma1688(acc[mt][1], a4, &b4[0][2]);
                mma1688(acc[mt][2], a4, &b4[1][0]);
                mma1688(acc[mt][3], a4, &b4[1][2]);
            }
        }
        __syncthreads();
    }

    const int rBase = m0 + wm*64 + (lane >> 2);
    const int cBase = n0 + wn*32 + (lane & 3)*2;
    #pragma unroll
    for (int mt=0; mt<4; mt++){
        const int r0 = rBase + mt*16;
        const float bi0 = bias[r0], bi1 = bias[r0+8];
        float* cp0 = C + ((size_t)z*M + r0  )*NHW;
        float* cp1 = C + ((size_t)z*M + r0+8)*NHW;
        const float* rp0 = res ? res + ((size_t)z*M + r0  )*NHW : nullptr;
        const float* rp1 = res ? res + ((size_t)z*M + r0+8)*NHW : nullptr;
        #pragma unroll
        for (int nt=0; nt<4; nt++){
            const int cc = cBase + nt*8;
            float2 v0 = make_float2(acc[mt][nt][0]+bi0, acc[mt][nt][1]+bi0);
            float2 v1 = make_float2(acc[mt][nt][2]+bi1, acc[mt][nt][3]+bi1);
            if (rp0){
                float2 a0 = *(const float2*)(rp0 + cc);
                float2 a1 = *(const float2*)(rp1 + cc);
                v0.x+=a0.x; v0.y+=a0.y; v1.x+=a1.x; v1.y+=a1.y;
            }
            *(float2*)(cp0 + cc) = v0;
            *(float2*)(cp1 + cc) = v1;
        }
    }
}

// ============================================================================
// TF32 flash attention. Block per (q-tile 128, bh); 8 warps, warp = 16q x 128m.
// Q/K [row][64+pad] tf32; V native [d 64][m 1024] (double-buffered tile);
// P fp32 in smem (warp-private rows). Epilogue writes proj-B layout directly.
// ============================================================================
#define AQK 68                          // Q/K row stride (floats)
#define AVP 132                         // V/P row stride (floats)
#define OFF_K (128*AQK)                 // 8704
#define OFF_V0 (2*128*AQK)              // 17408
#define OFF_V1 (OFF_V0 + 64*AVP)        // 25856
#define OFF_P  (OFF_V1 + 64*AVP)        // 34304
#define ATT_SMEM ((OFF_P + 128*AVP)*4)  // 204800 B

__global__ void __launch_bounds__(256)
attn_mma_kernel(const float* __restrict__ QT,
                const float* __restrict__ KT,
                const float* __restrict__ qkv,
                float* __restrict__ OutB)
{
    extern __shared__ float smf[];
    const int tid = threadIdx.x, warp = tid >> 5, lane = tid & 31;
    const int q0 = blockIdx.x*128, bh = blockIdx.y;
    const int z = bh >> 3, h = bh & 7;
    const int qrow = warp*16;

    const float* Qg = QT + ((size_t)bh*NHW + q0)*HD;
    const float* Kg = KT + (size_t)bh*NHW*HD;
    const float* Vg = qkv + ((size_t)z*3*NC + 2*NC + h*HD)*NHW;

    const uint32_t sQa = smem_u32(smf);
    const uint32_t sKa = sQa + OFF_K*4;
    const uint32_t sV0 = sQa + OFF_V0*4;
    const uint32_t sV1 = sQa + OFF_V1*4;
    float* sP = smf + OFF_P;
    const uint32_t sPa = sQa + OFF_P*4;

    auto issueK = [&](int mm0){
        #pragma unroll
        for (int it=0; it<8; it++){
            int i = tid + it*256;
            int row = i >> 4, seg = (i & 15)*4;
            cpa16(sKa + (uint32_t)(row*AQK + seg)*4,
                  Kg + (size_t)(mm0+row)*HD + seg);
        }
    };
    auto issueV = [&](int mm0, uint32_t dst){
        #pragma unroll
        for (int it=0; it<8; it++){
            int i = tid + it*256;
            int row = i >> 5, seg = (i & 31)*4;
            cpa16(dst + (uint32_t)(row*AVP + seg)*4,
                  Vg + (size_t)row*NHW + mm0 + seg);
        }
    };

    // prologue: Q + K0 + V0
    #pragma unroll
    for (int it=0; it<8; it++){
        int i = tid + it*256;
        int row = i >> 4, seg = (i & 15)*4;
        cpa16(sQa + (uint32_t)(row*AQK + seg)*4, Qg + (size_t)row*HD + seg);
    }
    issueK(0);
    issueV(0, sV0);
    CP_COMMIT();
    CP_WAIT0();
    __syncthreads();

    const int rowA = (lane&7) + ((lane>>3)&1)*8;
    const int colA = ((lane>>4)&1)*4;
    const int rowB = (lane&7) + ((lane>>4)&1)*8;
    const int colB = ((lane>>3)&1)*4;
    const uint32_t aQ = sQa + ((qrow + rowA)*AQK + colA)*4;
    const uint32_t bK = sKa + (rowB*AQK + colB)*4;
    const uint32_t aP = sPa + ((qrow + rowA)*AVP + colA)*4;
    const uint32_t bVoff = (uint32_t)(rowB*AVP + colB)*4;

    float m0r = -1e30f, m1r = -1e30f, l0r = 0.f, l1r = 0.f;
    float o[8][4];
    #pragma unroll
    for (int i=0;i<8;i++){ o[i][0]=0.f; o[i][1]=0.f; o[i][2]=0.f; o[i][3]=0.f; }

    const int r0 = qrow + (lane>>2);
    const int pcol = (lane&3)*2;

    for (int t = 0; t < 8; t++){
        // ---- S = Q K^T ----
        float s[16][4];
        #pragma unroll
        for (int i=0;i<16;i++){ s[i][0]=0.f; s[i][1]=0.f; s[i][2]=0.f; s[i][3]=0.f; }

        #pragma unroll
        for (int k8=0; k8<8; k8++){
            const uint32_t kb = k8*32;
            uint32_t qa[4];
            ldmx4(qa, aQ + kb);
            #pragma unroll
            for (int p=0; p<8; p++){
                uint32_t k4[4];
                ldmx4(k4, bK + p*(16*AQK*4) + kb);
                mma1688(s[2*p],   qa, &k4[0]);
                mma1688(s[2*p+1], qa, &k4[2]);
            }
        }
        __syncthreads();                      // all warps done reading sK
        if (t < 7){
            issueK((t+1)*128);
            issueV((t+1)*128, (t&1) ? sV0 : sV1);
            CP_COMMIT();
        }

        // ---- online softmax (warp-local rows); P stored fp32(tf32-rna) ----
        {
            float mx = -1e30f;
            #pragma unroll
            for (int nt=0; nt<16; nt++) mx = fmaxf(mx, fmaxf(s[nt][0], s[nt][1]));
            mx = fmaxf(mx, __shfl_xor_sync(0xffffffffu, mx, 1));
            mx = fmaxf(mx, __shfl_xor_sync(0xffffffffu, mx, 2));
            float mn = fmaxf(m0r, mx);
            float corr = __expf(m0r - mn);
            m0r = mn;
            float sum = 0.f;
            #pragma unroll
            for (int nt=0; nt<16; nt++){
                float p0 = __expf(s[nt][0]-mn), p1 = __expf(s[nt][1]-mn);
                sum += p0+p1;
                *(float2*)&sP[r0*AVP + nt*8 + pcol] = make_float2(rtf(p0), rtf(p1));
            }
            sum += __shfl_xor_sync(0xffffffffu, sum, 1);
            sum += __shfl_xor_sync(0xffffffffu, sum, 2);
            l0r = l0r*corr + sum;
            #pragma unroll
            for (int i=0;i<8;i++){ o[i][0]*=corr; o[i][1]*=corr; }
        }
        {
            float mx = -1e30f;
            #pragma unroll
            for (int nt=0; nt<16; nt++) mx = fmaxf(mx, fmaxf(s[nt][2], s[nt][3]));
            mx = fmaxf(mx, __shfl_xor_sync(0xffffffffu, mx, 1));
            mx = fmaxf(mx, __shfl_xor_sync(0xffffffffu, mx, 2));
            float mn = fmaxf(m1r, mx);
            float corr = __expf(m1r - mn);
            m1r = mn;
            float sum = 0.f;
            #pragma unroll
            for (int nt=0; nt<16; nt++){
                float p0 = __expf(s[nt][2]-mn), p1 = __expf(s[nt][3]-mn);
                sum += p0+p1;
                *(float2*)&sP[(r0+8)*AVP + nt*8 + pcol] = make_float2(rtf(p0), rtf(p1));
            }
            sum += __shfl_xor_sync(0xffffffffu, sum, 1);
            sum += __shfl_xor_sync(0xffffffffu, sum, 2);
            l1r = l1r*corr + sum;
            #pragma unroll
            for (int i=0;i<8;i++){ o[i][2]*=corr; o[i][3]*=corr; }
        }
        __syncwarp();                         // P rows are warp-private

        // ---- O += P V^T ; V(t) in buffer t&1 ----
        const uint32_t bV = ((t&1) ? sV1 : sV0) + bVoff;
        #pragma unroll
        for (int k8=0; k8<16; k8++){
            const uint32_t kb = k8*32;
            uint32_t pa[4];
            ldmx4(pa, aP + kb);
            #pragma unroll
            for (int p=0; p<4; p++){
                uint32_t v4[4];
                ldmx4(v4, bV + p*(16*AVP*4) + kb);
                mma1688(o[2*p],   pa, &v4[0]);
                mma1688(o[2*p+1], pa, &v4[2]);
            }
        }
        if (t < 7) CP_WAIT0();
        __syncthreads();
    }

    // ---- normalize, write proj-B layout [z][n=q][512] with rna ----
    float inv0 = 1.f/l0r, inv1 = 1.f/l1r;
    float* ob = OutB + ((size_t)z*NHW + q0)*NC + h*HD;
    #pragma unroll
    for (int nt=0; nt<8; nt++){
        int d = nt*8 + pcol;
        *(float2*)&ob[(size_t)r0*NC + d] =
            make_float2(rtf(o[nt][0]*inv0), rtf(o[nt][1]*inv0));
        *(float2*)&ob[(size_t)(r0+8)*NC + d] =
            make_float2(rtf(o[nt][2]*inv1), rtf(o[nt][3]*inv1));
    }
}

// ============================================================================
extern "C" void kernel_launch(void* const* d_in, const int* in_sizes, int n_in,
                              void* d_out, int out_size)
{
    const float* x      = (const float*)d_in[0];
    const float* gn_w   = (const float*)d_in[1];
    const float* gn_b   = (const float*)d_in[2];
    const float* qkv_w  = (const float*)d_in[3];
    const float* qkv_b  = (const float*)d_in[4];
    const float* proj_w = (const float*)d_in[5];
    const float* proj_b = (const float*)d_in[6];
    float* out = (float*)d_out;

    float *qkv, *attB, *wAf, *wPf, *xnT, *QT, *KT;
    cudaGetSymbolAddress((void**)&qkv,  g_qkv);
    cudaGetSymbolAddress((void**)&attB, g_attB);
    cudaGetSymbolAddress((void**)&wAf,  g_wAf);
    cudaGetSymbolAddress((void**)&wPf,  g_wPf);
    cudaGetSymbolAddress((void**)&xnT,  g_xnT);
    cudaGetSymbolAddress((void**)&QT,   g_QT);
    cudaGetSymbolAddress((void**)&KT,   g_KT);

    static int attr_set = 0;
    if (!attr_set){
        cudaFuncSetAttribute(attn_mma_kernel,
            cudaFuncAttributeMaxDynamicSharedMemorySize, ATT_SMEM);
        cudaFuncSetAttribute(mma_gemm_kernel,
            cudaFuncAttributeMaxDynamicSharedMemorySize, GEMM_SMEM);
        attr_set = 1;
    }

    // 1. GroupNorm stats
    gn_stats_kernel<<<NB*NG, 256>>>(x);

    // 2. qkv weights -> rna tf32; fused GN-apply + transpose of x
    conv_w_kernel<<<(3*NC*NC)/1024, 256>>>(qkv_w, wAf, 3*NC*NC);
    conv_xnT_kernel<<<dim3(32, 16, NB), dim3(32,8)>>>(x, gn_w, gn_b, xnT);

    // 3. QKV GEMM (tf32)  [launch #4 -> ncu-profiled]
    mma_gemm_kernel<<<dim3(8, 12, NB), 256, GEMM_SMEM>>>(wAf, xnT, qkv_b,
                                                         nullptr, qkv, 3*NC);

    // 4. Q (scaled) + K transposes; V consumed in native layout
    conv_qkT_kernel<<<dim3(32, 2, 2*NB*NH), dim3(32,8)>>>(qkv, QT, KT);

    // 5. TF32 flash attention -> attB (proj-B layout)
    attn_mma_kernel<<<dim3(8, NB*NH), 256, ATT_SMEM>>>(QT, KT, qkv, attB);

    // 6. proj weights; proj GEMM + residual -> out
    conv_w_kernel<<<(NC*NC)/1024, 256>>>(proj_w, wPf, NC*NC);
    mma_gemm_kernel<<<dim3(8, 4, NB), 256, GEMM_SMEM>>>(wPf, attB, proj_b,
                                                        x, out, NC);
}

// round 13
// speedup vs baseline: 1.4058x; 1.1746x over previous
#include <cuda_runtime.h>
#include <cuda_bf16.h>
#include <cstdint>

#define NB   8
#define NC   512
#define NHW  1024
#define NH   8
#define HD   64
#define NG   32
#define CPG  16

// -------- scratch (static device arrays; no cudaMalloc allowed) --------
__device__ float g_qkv [NB*3*NC*NHW];           // 48 MB qkv activations fp32
__device__ float g_attB[NB*NHW*NC];             // 16 MB attn out, proj-B layout [z][n][512]
__device__ float g_mu[NB*NG], g_rs[NB*NG];      // groupnorm stats
__device__ float g_wAf[3*NC*NC];                //  3 MB qkv_w rna-tf32 [1536][512]
__device__ float g_wPf[NC*NC];                  //  1 MB proj_w rna-tf32 [512][512]
__device__ float g_xnT[NB*NHW*NC];              // 16 MB xn^T [z][1024][512]
__device__ float g_QT [NB*NH*NHW*HD];           // 16 MB Q^T/8 [bh][1024][64]
__device__ float g_KT [NB*NH*NHW*HD];           // 16 MB K^T   [bh][1024][64]

// -------- helpers --------
__device__ __forceinline__ uint32_t smem_u32(const void* p){
    uint32_t a;
    asm("{ .reg .u64 t; cvta.to.shared.u64 t, %1; cvt.u32.u64 %0, t; }"
        : "=r"(a) : "l"(p));
    return a;
}
__device__ __forceinline__ void ldmx4(uint32_t* r, uint32_t addr){
    asm volatile("ldmatrix.sync.aligned.m8n8.x4.shared.b16 {%0,%1,%2,%3}, [%4];"
        : "=r"(r[0]),"=r"(r[1]),"=r"(r[2]),"=r"(r[3]) : "r"(addr));
}
__device__ __forceinline__ void mma1688(float* d, const uint32_t* a, const uint32_t* b){
    asm volatile("mma.sync.aligned.m16n8k8.row.col.f32.tf32.tf32.f32 "
        "{%0,%1,%2,%3}, {%4,%5,%6,%7}, {%8,%9}, {%0,%1,%2,%3};"
        : "+f"(d[0]),"+f"(d[1]),"+f"(d[2]),"+f"(d[3])
        : "r"(a[0]),"r"(a[1]),"r"(a[2]),"r"(a[3]), "r"(b[0]),"r"(b[1]));
}
__device__ __forceinline__ float rtf(float x){
    uint32_t y; asm("cvt.rna.tf32.f32 %0, %1;" : "=r"(y) : "f"(x));
    return __uint_as_float(y);
}
__device__ __forceinline__ void cpa16(uint32_t s, const void* g){
    asm volatile("cp.async.cg.shared.global [%0], [%1], 16;" :: "r"(s), "l"(g));
}
#define CP_COMMIT() asm volatile("cp.async.commit_group;" ::: "memory")
#define CP_WAIT0()  asm volatile("cp.async.wait_group 0;" ::: "memory")

// ============================================================================
// GroupNorm stats (validated)
// ============================================================================
__global__ void __launch_bounds__(256)
gn_stats_kernel(const float* __restrict__ x)
{
    const int GSZ4 = CPG*NHW/4;
    int bg = blockIdx.x;
    const float4* xp = (const float4*)(x + (size_t)bg*CPG*NHW);

    float s = 0.f, s2 = 0.f;
    for (int i = threadIdx.x; i < GSZ4; i += 256){
        float4 v = xp[i];
        s  += (v.x+v.y)+(v.z+v.w);
        s2 += (v.x*v.x+v.y*v.y)+(v.z*v.z+v.w*v.w);
    }
    #pragma unroll
    for (int m=16;m;m>>=1){
        s  += __shfl_xor_sync(0xffffffffu, s,  m);
        s2 += __shfl_xor_sync(0xffffffffu, s2, m);
    }
    __shared__ float shA[8], shB[8];
    int w = threadIdx.x>>5, l = threadIdx.x&31;
    if (l==0){ shA[w]=s; shB[w]=s2; }
    __syncthreads();
    if (threadIdx.x==0){
        float S=0.f, S2=0.f;
        #pragma unroll
        for (int i=0;i<8;i++){ S+=shA[i]; S2+=shB[i]; }
        const float inv = 1.f/(float)(CPG*NHW);
        float mu  = S*inv;
        float var = S2*inv - mu*mu;
        g_mu[bg] = mu;
        g_rs[bg] = rsqrtf(var + 1e-5f);
    }
}

// ============================================================================
// Weight converter: rna fp32 -> tf32 bit pattern
// ============================================================================
__global__ void __launch_bounds__(256)
conv_w_kernel(const float* __restrict__ w, float* __restrict__ o, int total)
{
    int i = (blockIdx.x*256 + threadIdx.x)*4;
    if (i >= total) return;
    float4 v = *(const float4*)(w + i);
    *(float4*)(o + i) = make_float4(rtf(v.x), rtf(v.y), rtf(v.z), rtf(v.w));
}

// ============================================================================
// Fused GroupNorm-apply + transpose: x [z][512][1024] -> [z][1024 n][512 k] tf32
// ============================================================================
__global__ void __launch_bounds__(256)
conv_xnT_kernel(const float* __restrict__ x,
                const float* __restrict__ gw,
                const float* __restrict__ gb,
                float* __restrict__ out)
{
    __shared__ float t[32][33];
    int n0 = blockIdx.x*32, k0 = blockIdx.y*32, z = blockIdx.z;
    int tx = threadIdx.x, ty = threadIdx.y;
    const float* ip = x + ((size_t)z*NC + k0)*NHW + n0;
    #pragma unroll
    for (int j=0;j<4;j++)
        t[ty*4+j][tx] = ip[(size_t)(ty*4+j)*NHW + tx];
    __syncthreads();
    const int c = k0 + tx;
    const int g = c >> 4;
    float mu = g_mu[z*NG+g], rs = g_rs[z*NG+g];
    float a = gw[c]*rs, off = gb[c] - mu*a;
    float* op = out + ((size_t)z*NHW + n0)*NC + k0;
    #pragma unroll
    for (int j=0;j<4;j++){
        int nl = ty*4+j;
        op[(size_t)nl*NC + tx] = rtf(t[tx][nl]*a + off);
    }
}

// ============================================================================
// Q+K transpose: z<64 -> Q (scale 1/8), z>=64 -> K. out [bh][1024 n][64 d] tf32
// ============================================================================
__global__ void __launch_bounds__(256)
conv_qkT_kernel(const float* __restrict__ in,
                float* __restrict__ outQ,
                float* __restrict__ outK)
{
    __shared__ float t[32][33];
    int zz = blockIdx.z;
    int isK = zz >= NB*NH;
    int bh = zz & 63;
    int b = bh >> 3, h = bh & 7;
    int coff  = isK ? NC : 0;
    float scale = isK ? 1.0f : 0.125f;
    float* out = isK ? outK : outQ;

    int n0 = blockIdx.x*32, d0 = blockIdx.y*32;
    int tx = threadIdx.x, ty = threadIdx.y;
    const float* ip = in + ((size_t)b*3*NC + coff + h*HD + d0)*NHW + n0;
    #pragma unroll
    for (int j=0;j<4;j++)
        t[ty*4+j][tx] = ip[(size_t)(ty*4+j)*NHW + tx];
    __syncthreads();
    float* op = out + ((size_t)bh*NHW + n0)*HD + d0;
    #pragma unroll
    for (int j=0;j<4;j++){
        int nl = ty*4+j;
        op[(size_t)nl*HD + tx] = rtf(t[tx][nl]*scale);
    }
}

// ============================================================================
// TF32 GEMM: C[z][m][n] = A[m][:512] * B[z][n][:512]^T + bias[m] (+ res)
// 128x128 tile, K-chunks of 32, 2-stage cp.async, 2 CTAs/SM.
// ============================================================================
#define GST 36                          // floats per smem row (144 B)
#define GTE (128*GST)                   // 4608 floats per tile
#define GSTAGE (2*GTE)                  // A+B per stage
#define GEMM_SMEM (2*GSTAGE*4)          // 73728 B -> 2 CTAs/SM

__global__ void __launch_bounds__(256,2)
mma_gemm_kernel(const float* __restrict__ A2,
                const float* __restrict__ B2t,
                const float* __restrict__ bias,
                const float* __restrict__ res,
                float* __restrict__ C,
                int M)
{
    extern __shared__ float smf[];
    const int tid  = threadIdx.x;
    const int warp = tid >> 5, lane = tid & 31;
    const int wm = warp >> 2, wn = warp & 3;
    const int n0 = blockIdx.x*128, m0 = blockIdx.y*128, z = blockIdx.z;

    const float* Ag = A2 + (size_t)m0*NC;
    const float* Bg = B2t + ((size_t)z*NHW + n0)*NC;

    const uint32_t smBase = smem_u32(smf);
    const int rowA = (lane&7) + ((lane>>3)&1)*8;
    const int colA = ((lane>>4)&1)*4;
    const int rowB = (lane&7) + ((lane>>4)&1)*8;
    const int colB = ((lane>>3)&1)*4;
    const uint32_t aBase = smBase + ((wm*64 + rowA)*GST + colA)*4;
    const uint32_t bBase = smBase + GTE*4 + ((wn*32 + rowB)*GST + colB)*4;

    auto issue_chunk = [&](int c){
        const uint32_t base = smBase + (c & 1)*GSTAGE*4;
        const int kh = c*32;
        #pragma unroll
        for (int it=0; it<4; it++){
            int i = tid + it*256;
            int row = i >> 3, seg = (i & 7)*4;
            cpa16(base + (uint32_t)(row*GST + seg)*4,
                  Ag + (size_t)row*NC + kh + seg);
            cpa16(base + GTE*4 + (uint32_t)(row*GST + seg)*4,
                  Bg + (size_t)row*NC + kh + seg);
        }
        CP_COMMIT();
    };

    float acc[4][4][4];
    #pragma unroll
    for (int i=0;i<4;i++)
        #pragma unroll
        for (int j=0;j<4;j++)
            #pragma unroll
            for (int r=0;r<4;r++) acc[i][j][r]=0.f;

    issue_chunk(0);

    for (int c = 0; c < 16; c++){
        CP_WAIT0();
        __syncthreads();
        if (c < 15) issue_chunk(c+1);

        const uint32_t so = (c & 1)*GSTAGE*4;
        #pragma unroll
        for (int k8 = 0; k8 < 4; k8++){
            const uint32_t kb = k8*32;
            uint32_t b4[2][4];
            ldmx4(b4[0], bBase + so + kb);
            ldmx4(b4[1], bBase + so + 16*GST*4 + kb);
            #pragma unroll
            for (int mt=0; mt<4; mt++){
                uint32_t a4[4];
                ldmx4(a4, aBase + so + mt*(16*GST*4) + kb);
                mma1688(acc[mt][0], a4, &b4[0][0]);
                mma1688(acc[mt][1], a4, &b4[0][2]);
                mma1688(acc[mt][2], a4, &b4[1][0]);
                mma1688(acc[mt][3], a4, &b4[1][2]);
            }
        }
    }

    const int rBase = m0 + wm*64 + (lane >> 2);
    const int cBase = n0 + wn*32 + (lane & 3)*2;
    #pragma unroll
    for (int mt=0; mt<4; mt++){
        const int r0 = rBase + mt*16;
        const float bi0 = bias[r0], bi1 = bias[r0+8];
        float* cp0 = C + ((size_t)z*M + r0  )*NHW;
        float* cp1 = C + ((size_t)z*M + r0+8)*NHW;
        const float* rp0 = res ? res + ((size_t)z*M + r0  )*NHW : nullptr;
        const float* rp1 = res ? res + ((size_t)z*M + r0+8)*NHW : nullptr;
        #pragma unroll
        for (int nt=0; nt<4; nt++){
            const int cc = cBase + nt*8;
            float2 v0 = make_float2(acc[mt][nt][0]+bi0, acc[mt][nt][1]+bi0);
            float2 v1 = make_float2(acc[mt][nt][2]+bi1, acc[mt][nt][3]+bi1);
            if (rp0){
                float2 a0 = *(const float2*)(rp0 + cc);
                float2 a1 = *(const float2*)(rp1 + cc);
                v0.x+=a0.x; v0.y+=a0.y; v1.x+=a1.x; v1.y+=a1.y;
            }
            *(float2*)(cp0 + cc) = v0;
            *(float2*)(cp1 + cc) = v1;
        }
    }
}

// ============================================================================
// TF32 flash attention, m-tile 64, Q in registers, 2 CTAs/SM.
// Block per (q-tile 128, bh); 8 warps, warp = 16q x 64m.
// smem: K[2][64x68] + V[2][64x68] + P[128x68] = 104448 B.
// ============================================================================
#define AKV 68
#define KTE (64*AKV)                    // 4352 floats per tile
#define OFF_V (2*KTE)
#define OFF_P (4*KTE)
#define ATT_SMEM ((OFF_P + 128*AKV)*4)  // 104448 B

__global__ void __launch_bounds__(256,2)
attn_mma_kernel(const float* __restrict__ QT,
                const float* __restrict__ KT,
                const float* __restrict__ qkv,
                float* __restrict__ OutB)
{
    extern __shared__ float smf[];
    const int tid = threadIdx.x, warp = tid >> 5, lane = tid & 31;
    const int q0 = blockIdx.x*128, bh = blockIdx.y;
    const int z = bh >> 3, h = bh & 7;
    const int qrow = warp*16;

    const float* Qg = QT + ((size_t)bh*NHW + q0)*HD;
    const float* Kg = KT + (size_t)bh*NHW*HD;
    const float* Vg = qkv + ((size_t)z*3*NC + 2*NC + h*HD)*NHW;

    const uint32_t smBase = smem_u32(smf);
    const uint32_t sK[2] = { smBase, smBase + KTE*4 };
    const uint32_t sV[2] = { smBase + OFF_V*4, smBase + (OFF_V+KTE)*4 };
    float* sP = smf + OFF_P;
    const uint32_t sPa = smBase + OFF_P*4;

    auto issueK = [&](int mm0, uint32_t dst){
        #pragma unroll
        for (int it=0; it<4; it++){
            int i = tid + it*256;
            int row = i >> 4, seg = (i & 15)*4;
            cpa16(dst + (uint32_t)(row*AKV + seg)*4,
                  Kg + (size_t)(mm0+row)*HD + seg);
        }
    };
    auto issueV = [&](int mm0, uint32_t dst){
        #pragma unroll
        for (int it=0; it<4; it++){
            int i = tid + it*256;
            int row = i >> 4, seg = (i & 15)*4;
            cpa16(dst + (uint32_t)(row*AKV + seg)*4,
                  Vg + (size_t)row*NHW + mm0 + seg);
        }
    };

    // prologue: stage Q in P region; K0,V0
    #pragma unroll
    for (int it=0; it<8; it++){
        int i = tid + it*256;
        int row = i >> 4, seg = (i & 15)*4;
        cpa16(sPa + (uint32_t)(row*AKV + seg)*4, Qg + (size_t)row*HD + seg);
    }
    issueK(0, sK[0]);
    issueV(0, sV[0]);
    CP_COMMIT();
    CP_WAIT0();
    __syncthreads();

    const int rowA = (lane&7) + ((lane>>3)&1)*8;
    const int colA = ((lane>>4)&1)*4;
    const int rowB = (lane&7) + ((lane>>4)&1)*8;
    const int colB = ((lane>>3)&1)*4;

    // Q fragments in registers (A-frag per k8 step)
    uint32_t qf[8][4];
    {
        const uint32_t aQ = sPa + ((qrow + rowA)*AKV + colA)*4;
        #pragma unroll
        for (int k8=0; k8<8; k8++) ldmx4(qf[k8], aQ + k8*32);
    }
    const uint32_t aP    = sPa + ((qrow + rowA)*AKV + colA)*4;
    const uint32_t bOffP = (uint32_t)(rowB*AKV + colB)*4;

    float m0r = -1e30f, m1r = -1e30f, l0r = 0.f, l1r = 0.f;
    float o[8][4];
    #pragma unroll
    for (int i=0;i<8;i++){ o[i][0]=0.f; o[i][1]=0.f; o[i][2]=0.f; o[i][3]=0.f; }

    const int r0 = qrow + (lane>>2);
    const int pcol = (lane&3)*2;

    // note: qf build reads P rows qrow..qrow+15 (warp-private) before any P
    // store; first P store is by the same warp -> program order suffices.
    __syncthreads();

    for (int t = 0; t < 16; t++){
        if (t < 15){
            issueK((t+1)*64, sK[(t+1)&1]);
            issueV((t+1)*64, sV[(t+1)&1]);
            CP_COMMIT();
        }
        const uint32_t bK = sK[t&1] + bOffP;

        // ---- S = Q K^T (16q x 64m) ----
        float s[8][4];
        #pragma unroll
        for (int i=0;i<8;i++){ s[i][0]=0.f; s[i][1]=0.f; s[i][2]=0.f; s[i][3]=0.f; }

        #pragma unroll
        for (int k8=0; k8<8; k8++){
            const uint32_t kb = k8*32;
            #pragma unroll
            for (int p=0; p<4; p++){
                uint32_t k4[4];
                ldmx4(k4, bK + p*(16*AKV*4) + kb);
                mma1688(s[2*p],   qf[k8], &k4[0]);
                mma1688(s[2*p+1], qf[k8], &k4[2]);
            }
        }

        // ---- online softmax (warp-local rows) ----
        {
            float mx = -1e30f;
            #pragma unroll
            for (int nt=0; nt<8; nt++) mx = fmaxf(mx, fmaxf(s[nt][0], s[nt][1]));
            mx = fmaxf(mx, __shfl_xor_sync(0xffffffffu, mx, 1));
            mx = fmaxf(mx, __shfl_xor_sync(0xffffffffu, mx, 2));
            float mn = fmaxf(m0r, mx);
            float corr = __expf(m0r - mn);
            m0r = mn;
            float sum = 0.f;
            #pragma unroll
            for (int nt=0; nt<8; nt++){
                float p0 = __expf(s[nt][0]-mn), p1 = __expf(s[nt][1]-mn);
                sum += p0+p1;
                *(float2*)&sP[r0*AKV + nt*8 + pcol] = make_float2(rtf(p0), rtf(p1));
            }
            sum += __shfl_xor_sync(0xffffffffu, sum, 1);
            sum += __shfl_xor_sync(0xffffffffu, sum, 2);
            l0r = l0r*corr + sum;
            #pragma unroll
            for (int i=0;i<8;i++){ o[i][0]*=corr; o[i][1]*=corr; }
        }
        {
            float mx = -1e30f;
            #pragma unroll
            for (int nt=0; nt<8; nt++) mx = fmaxf(mx, fmaxf(s[nt][2], s[nt][3]));
            mx = fmaxf(mx, __shfl_xor_sync(0xffffffffu, mx, 1));
            mx = fmaxf(mx, __shfl_xor_sync(0xffffffffu, mx, 2));
            float mn = fmaxf(m1r, mx);
            float corr = __expf(m1r - mn);
            m1r = mn;
            float sum = 0.f;
            #pragma unroll
            for (int nt=0; nt<8; nt++){
                float p0 = __expf(s[nt][2]-mn), p1 = __expf(s[nt][3]-mn);
                sum += p0+p1;
                *(float2*)&sP[(r0+8)*AKV + nt*8 + pcol] = make_float2(rtf(p0), rtf(p1));
            }
            sum += __shfl_xor_sync(0xffffffffu, sum, 1);
            sum += __shfl_xor_sync(0xffffffffu, sum, 2);
            l1r = l1r*corr + sum;
            #pragma unroll
            for (int i=0;i<8;i++){ o[i][2]*=corr; o[i][3]*=corr; }
        }
        __syncwarp();                         // P rows are warp-private

        // ---- O += P V^T (16q x 64d, k = m 64) ----
        const uint32_t bV = sV[t&1] + bOffP;
        #pragma unroll
        for (int k8=0; k8<8; k8++){
            const uint32_t kb = k8*32;
            uint32_t pa[4];
            ldmx4(pa, aP + kb);
            #pragma unroll
            for (int p=0; p<4; p++){
                uint32_t v4[4];
                ldmx4(v4, bV + p*(16*AKV*4) + kb);
                mma1688(o[2*p],   pa, &v4[0]);
                mma1688(o[2*p+1], pa, &v4[2]);
            }
        }
        if (t < 15) CP_WAIT0();
        __syncthreads();
    }

    // ---- normalize, write proj-B layout [z][n=q][512] ----
    float inv0 = 1.f/l0r, inv1 = 1.f/l1r;
    float* ob = OutB + ((size_t)z*NHW + q0)*NC + h*HD;
    #pragma unroll
    for (int nt=0; nt<8; nt++){
        int d = nt*8 + pcol;
        *(float2*)&ob[(size_t)r0*NC + d] =
            make_float2(rtf(o[nt][0]*inv0), rtf(o[nt][1]*inv0));
        *(float2*)&ob[(size_t)(r0+8)*NC + d] =
            make_float2(rtf(o[nt][2]*inv1), rtf(o[nt][3]*inv1));
    }
}

// ============================================================================
extern "C" void kernel_launch(void* const* d_in, const int* in_sizes, int n_in,
                              void* d_out, int out_size)
{
    const float* x      = (const float*)d_in[0];
    const float* gn_w   = (const float*)d_in[1];
    const float* gn_b   = (const float*)d_in[2];
    const float* qkv_w  = (const float*)d_in[3];
    const float* qkv_b  = (const float*)d_in[4];
    const float* proj_w = (const float*)d_in[5];
    const float* proj_b = (const float*)d_in[6];
    float* out = (float*)d_out;

    float *qkv, *attB, *wAf, *wPf, *xnT, *QT, *KT;
    cudaGetSymbolAddress((void**)&qkv,  g_qkv);
    cudaGetSymbolAddress((void**)&attB, g_attB);
    cudaGetSymbolAddress((void**)&wAf,  g_wAf);
    cudaGetSymbolAddress((void**)&wPf,  g_wPf);
    cudaGetSymbolAddress((void**)&xnT,  g_xnT);
    cudaGetSymbolAddress((void**)&QT,   g_QT);
    cudaGetSymbolAddress((void**)&KT,   g_KT);

    static int attr_set = 0;
    if (!attr_set){
        cudaFuncSetAttribute(attn_mma_kernel,
            cudaFuncAttributeMaxDynamicSharedMemorySize, ATT_SMEM);
        cudaFuncSetAttribute(mma_gemm_kernel,
            cudaFuncAttributeMaxDynamicSharedMemorySize, GEMM_SMEM);
        attr_set = 1;
    }

    // 1. GroupNorm stats
    gn_stats_kernel<<<NB*NG, 256>>>(x);

    // 2. qkv weights -> tf32; fused GN-apply + transpose of x
    conv_w_kernel<<<(3*NC*NC)/1024, 256>>>(qkv_w, wAf, 3*NC*NC);
    conv_xnT_kernel<<<dim3(32, 16, NB), dim3(32,8)>>>(x, gn_w, gn_b, xnT);

    // 3. QKV GEMM (tf32, 2 CTA/SM)
    mma_gemm_kernel<<<dim3(8, 12, NB), 256, GEMM_SMEM>>>(wAf, xnT, qkv_b,
                                                         nullptr, qkv, 3*NC);

    // 4. Q (scaled) + K transposes; V consumed in native layout
    conv_qkT_kernel<<<dim3(32, 2, 2*NB*NH), dim3(32,8)>>>(qkv, QT, KT);

    // 5. TF32 flash attention (2 CTA/SM) -> attB (proj-B layout)
    attn_mma_kernel<<<dim3(8, NB*NH), 256, ATT_SMEM>>>(QT, KT, qkv, attB);

    // 6. proj weights; proj GEMM + residual -> out
    conv_w_kernel<<<(NC*NC)/1024, 256>>>(proj_w, wPf, NC*NC);
    mma_gemm_kernel<<<dim3(8, 4, NB), 256, GEMM_SMEM>>>(wPf, attB, proj_b,
                                                        x, out, NC);
}

// round 14
// speedup vs baseline: 1.4181x; 1.0088x over previous
#include <cuda_runtime.h>
#include <cuda_bf16.h>
#include <cstdint>

#define NB   8
#define NC   512
#define NHW  1024
#define NH   8
#define HD   64
#define NG   32
#define CPG  16

// -------- scratch (static device arrays; no cudaMalloc allowed) --------
__device__ float g_qkv [NB*3*NC*NHW];           // 48 MB qkv activations fp32
__device__ float g_attB[NB*NHW*NC];             // 16 MB attn out, proj-B layout [z][n][512]
__device__ float g_mu[NB*NG], g_rs[NB*NG];      // groupnorm stats
__device__ float g_wAf[3*NC*NC];                //  3 MB qkv_w rna-tf32 [1536][512]
__device__ float g_wPf[NC*NC];                  //  1 MB proj_w rna-tf32 [512][512]
__device__ float g_xnT[NB*NHW*NC];              // 16 MB xn^T [z][1024][512]
__device__ float g_QT [NB*NH*NHW*HD];           // 16 MB Q^T/8 [bh][1024][64]
__device__ float g_KT [NB*NH*NHW*HD];           // 16 MB K^T   [bh][1024][64]

// -------- helpers --------
__device__ __forceinline__ uint32_t smem_u32(const void* p){
    uint32_t a;
    asm("{ .reg .u64 t; cvta.to.shared.u64 t, %1; cvt.u32.u64 %0, t; }"
        : "=r"(a) : "l"(p));
    return a;
}
__device__ __forceinline__ void ldmx4(uint32_t* r, uint32_t addr){
    asm volatile("ldmatrix.sync.aligned.m8n8.x4.shared.b16 {%0,%1,%2,%3}, [%4];"
        : "=r"(r[0]),"=r"(r[1]),"=r"(r[2]),"=r"(r[3]) : "r"(addr));
}
__device__ __forceinline__ void mma1688(float* d, const uint32_t* a, const uint32_t* b){
    asm volatile("mma.sync.aligned.m16n8k8.row.col.f32.tf32.tf32.f32 "
        "{%0,%1,%2,%3}, {%4,%5,%6,%7}, {%8,%9}, {%0,%1,%2,%3};"
        : "+f"(d[0]),"+f"(d[1]),"+f"(d[2]),"+f"(d[3])
        : "r"(a[0]),"r"(a[1]),"r"(a[2]),"r"(a[3]), "r"(b[0]),"r"(b[1]));
}
__device__ __forceinline__ float rtf(float x){
    uint32_t y; asm("cvt.rna.tf32.f32 %0, %1;" : "=r"(y) : "f"(x));
    return __uint_as_float(y);
}
__device__ __forceinline__ void cpa16(uint32_t s, const void* g){
    asm volatile("cp.async.cg.shared.global [%0], [%1], 16;" :: "r"(s), "l"(g));
}
#define CP_COMMIT() asm volatile("cp.async.commit_group;" ::: "memory")
#define CP_WAIT0()  asm volatile("cp.async.wait_group 0;" ::: "memory")

// ============================================================================
// GroupNorm stats (validated)
// ============================================================================
__global__ void __launch_bounds__(256)
gn_stats_kernel(const float* __restrict__ x)
{
    const int GSZ4 = CPG*NHW/4;
    int bg = blockIdx.x;
    const float4* xp = (const float4*)(x + (size_t)bg*CPG*NHW);

    float s = 0.f, s2 = 0.f;
    for (int i = threadIdx.x; i < GSZ4; i += 256){
        float4 v = xp[i];
        s  += (v.x+v.y)+(v.z+v.w);
        s2 += (v.x*v.x+v.y*v.y)+(v.z*v.z+v.w*v.w);
    }
    #pragma unroll
    for (int m=16;m;m>>=1){
        s  += __shfl_xor_sync(0xffffffffu, s,  m);
        s2 += __shfl_xor_sync(0xffffffffu, s2, m);
    }
    __shared__ float shA[8], shB[8];
    int w = threadIdx.x>>5, l = threadIdx.x&31;
    if (l==0){ shA[w]=s; shB[w]=s2; }
    __syncthreads();
    if (threadIdx.x==0){
        float S=0.f, S2=0.f;
        #pragma unroll
        for (int i=0;i<8;i++){ S+=shA[i]; S2+=shB[i]; }
        const float inv = 1.f/(float)(CPG*NHW);
        float mu  = S*inv;
        float var = S2*inv - mu*mu;
        g_mu[bg] = mu;
        g_rs[bg] = rsqrtf(var + 1e-5f);
    }
}

// ============================================================================
// Weight converter: rna fp32 -> tf32 bit pattern
// ============================================================================
__global__ void __launch_bounds__(256)
conv_w_kernel(const float* __restrict__ w, float* __restrict__ o, int total)
{
    int i = (blockIdx.x*256 + threadIdx.x)*4;
    if (i >= total) return;
    float4 v = *(const float4*)(w + i);
    *(float4*)(o + i) = make_float4(rtf(v.x), rtf(v.y), rtf(v.z), rtf(v.w));
}

// ============================================================================
// Fused GroupNorm-apply + transpose: x [z][512][1024] -> [z][1024 n][512 k] tf32
// ============================================================================
__global__ void __launch_bounds__(256)
conv_xnT_kernel(const float* __restrict__ x,
                const float* __restrict__ gw,
                const float* __restrict__ gb,
                float* __restrict__ out)
{
    __shared__ float t[32][33];
    int n0 = blockIdx.x*32, k0 = blockIdx.y*32, z = blockIdx.z;
    int tx = threadIdx.x, ty = threadIdx.y;
    const float* ip = x + ((size_t)z*NC + k0)*NHW + n0;
    #pragma unroll
    for (int j=0;j<4;j++)
        t[ty*4+j][tx] = ip[(size_t)(ty*4+j)*NHW + tx];
    __syncthreads();
    const int c = k0 + tx;
    const int g = c >> 4;
    float mu = g_mu[z*NG+g], rs = g_rs[z*NG+g];
    float a = gw[c]*rs, off = gb[c] - mu*a;
    float* op = out + ((size_t)z*NHW + n0)*NC + k0;
    #pragma unroll
    for (int j=0;j<4;j++){
        int nl = ty*4+j;
        op[(size_t)nl*NC + tx] = rtf(t[tx][nl]*a + off);
    }
}

// ============================================================================
// Q+K transpose: z<64 -> Q (scale 1/8), z>=64 -> K. out [bh][1024 n][64 d] tf32
// ============================================================================
__global__ void __launch_bounds__(256)
conv_qkT_kernel(const float* __restrict__ in,
                float* __restrict__ outQ,
                float* __restrict__ outK)
{
    __shared__ float t[32][33];
    int zz = blockIdx.z;
    int isK = zz >= NB*NH;
    int bh = zz & 63;
    int b = bh >> 3, h = bh & 7;
    int coff  = isK ? NC : 0;
    float scale = isK ? 1.0f : 0.125f;
    float* out = isK ? outK : outQ;

    int n0 = blockIdx.x*32, d0 = blockIdx.y*32;
    int tx = threadIdx.x, ty = threadIdx.y;
    const float* ip = in + ((size_t)b*3*NC + coff + h*HD + d0)*NHW + n0;
    #pragma unroll
    for (int j=0;j<4;j++)
        t[ty*4+j][tx] = ip[(size_t)(ty*4+j)*NHW + tx];
    __syncthreads();
    float* op = out + ((size_t)bh*NHW + n0)*HD + d0;
    #pragma unroll
    for (int j=0;j<4;j++){
        int nl = ty*4+j;
        op[(size_t)nl*HD + tx] = rtf(t[tx][nl]*scale);
    }
}

// ============================================================================
// TF32 GEMM (validated R13): 128x128 tile, K-chunks of 32, 2-stage, 2 CTAs/SM
// ============================================================================
#define GST 36
#define GTE (128*GST)
#define GSTAGE (2*GTE)
#define GEMM_SMEM (2*GSTAGE*4)          // 73728 B

__global__ void __launch_bounds__(256,2)
mma_gemm_kernel(const float* __restrict__ A2,
                const float* __restrict__ B2t,
                const float* __restrict__ bias,
                const float* __restrict__ res,
                float* __restrict__ C,
                int M)
{
    extern __shared__ float smf[];
    const int tid  = threadIdx.x;
    const int warp = tid >> 5, lane = tid & 31;
    const int wm = warp >> 2, wn = warp & 3;
    const int n0 = blockIdx.x*128, m0 = blockIdx.y*128, z = blockIdx.z;

    const float* Ag = A2 + (size_t)m0*NC;
    const float* Bg = B2t + ((size_t)z*NHW + n0)*NC;

    const uint32_t smBase = smem_u32(smf);
    const int rowA = (lane&7) + ((lane>>3)&1)*8;
    const int colA = ((lane>>4)&1)*4;
    const int rowB = (lane&7) + ((lane>>4)&1)*8;
    const int colB = ((lane>>3)&1)*4;
    const uint32_t aBase = smBase + ((wm*64 + rowA)*GST + colA)*4;
    const uint32_t bBase = smBase + GTE*4 + ((wn*32 + rowB)*GST + colB)*4;

    auto issue_chunk = [&](int c){
        const uint32_t base = smBase + (c & 1)*GSTAGE*4;
        const int kh = c*32;
        #pragma unroll
        for (int it=0; it<4; it++){
            int i = tid + it*256;
            int row = i >> 3, seg = (i & 7)*4;
            cpa16(base + (uint32_t)(row*GST + seg)*4,
                  Ag + (size_t)row*NC + kh + seg);
            cpa16(base + GTE*4 + (uint32_t)(row*GST + seg)*4,
                  Bg + (size_t)row*NC + kh + seg);
        }
        CP_COMMIT();
    };

    float acc[4][4][4];
    #pragma unroll
    for (int i=0;i<4;i++)
        #pragma unroll
        for (int j=0;j<4;j++)
            #pragma unroll
            for (int r=0;r<4;r++) acc[i][j][r]=0.f;

    issue_chunk(0);

    for (int c = 0; c < 16; c++){
        CP_WAIT0();
        __syncthreads();
        if (c < 15) issue_chunk(c+1);

        const uint32_t so = (c & 1)*GSTAGE*4;
        #pragma unroll
        for (int k8 = 0; k8 < 4; k8++){
            const uint32_t kb = k8*32;
            uint32_t b4[2][4];
            ldmx4(b4[0], bBase + so + kb);
            ldmx4(b4[1], bBase + so + 16*GST*4 + kb);
            #pragma unroll
            for (int mt=0; mt<4; mt++){
                uint32_t a4[4];
                ldmx4(a4, aBase + so + mt*(16*GST*4) + kb);
                mma1688(acc[mt][0], a4, &b4[0][0]);
                mma1688(acc[mt][1], a4, &b4[0][2]);
                mma1688(acc[mt][2], a4, &b4[1][0]);
                mma1688(acc[mt][3], a4, &b4[1][2]);
            }
        }
    }

    const int rBase = m0 + wm*64 + (lane >> 2);
    const int cBase = n0 + wn*32 + (lane & 3)*2;
    #pragma unroll
    for (int mt=0; mt<4; mt++){
        const int r0 = rBase + mt*16;
        const float bi0 = bias[r0], bi1 = bias[r0+8];
        float* cp0 = C + ((size_t)z*M + r0  )*NHW;
        float* cp1 = C + ((size_t)z*M + r0+8)*NHW;
        const float* rp0 = res ? res + ((size_t)z*M + r0  )*NHW : nullptr;
        const float* rp1 = res ? res + ((size_t)z*M + r0+8)*NHW : nullptr;
        #pragma unroll
        for (int nt=0; nt<4; nt++){
            const int cc = cBase + nt*8;
            float2 v0 = make_float2(acc[mt][nt][0]+bi0, acc[mt][nt][1]+bi0);
            float2 v1 = make_float2(acc[mt][nt][2]+bi1, acc[mt][nt][3]+bi1);
            if (rp0){
                float2 a0 = *(const float2*)(rp0 + cc);
                float2 a1 = *(const float2*)(rp1 + cc);
                v0.x+=a0.x; v0.y+=a0.y; v1.x+=a1.x; v1.y+=a1.y;
            }
            *(float2*)(cp0 + cc) = v0;
            *(float2*)(cp1 + cc) = v1;
        }
    }
}

// ============================================================================
// TF32 flash attention v2: warp = 32q x 64m (K/V frags amortized over 2
// A-tiles -> 0.375 LDSM.x4 per MMA). Block = 256-q tile, 8 warps, 1 CTA/SM.
// smem: K[2]+V[2] (64x68 each) + P[256x68] + Q[256x68] = 208896 B.
// ============================================================================
#define AKV 68
#define KTE (64*AKV)                    // 4352 floats
#define OFF_V (2*KTE)
#define OFF_P (4*KTE)                   // 17408
#define OFF_Q (OFF_P + 256*AKV)         // 34816
#define ATT_SMEM ((OFF_Q + 256*AKV)*4)  // 208896 B

__global__ void __launch_bounds__(256,1)
attn_mma_kernel(const float* __restrict__ QT,
                const float* __restrict__ KT,
                const float* __restrict__ qkv,
                float* __restrict__ OutB)
{
    extern __shared__ float smf[];
    const int tid = threadIdx.x, warp = tid >> 5, lane = tid & 31;
    const int q0 = blockIdx.x*256, bh = blockIdx.y;
    const int z = bh >> 3, h = bh & 7;
    const int qrow = warp*32;

    const float* Qg = QT + ((size_t)bh*NHW + q0)*HD;
    const float* Kg = KT + (size_t)bh*NHW*HD;
    const float* Vg = qkv + ((size_t)z*3*NC + 2*NC + h*HD)*NHW;

    const uint32_t smBase = smem_u32(smf);
    const uint32_t sK[2] = { smBase, smBase + KTE*4 };
    const uint32_t sV[2] = { smBase + OFF_V*4, smBase + (OFF_V+KTE)*4 };
    float* sP = smf + OFF_P;
    const uint32_t sPa = smBase + OFF_P*4;
    const uint32_t sQa = smBase + OFF_Q*4;

    auto issueK = [&](int mm0, uint32_t dst){
        #pragma unroll
        for (int it=0; it<4; it++){
            int i = tid + it*256;
            int row = i >> 4, seg = (i & 15)*4;
            cpa16(dst + (uint32_t)(row*AKV + seg)*4,
                  Kg + (size_t)(mm0+row)*HD + seg);
        }
    };
    auto issueV = [&](int mm0, uint32_t dst){
        #pragma unroll
        for (int it=0; it<4; it++){
            int i = tid + it*256;
            int row = i >> 4, seg = (i & 15)*4;
            cpa16(dst + (uint32_t)(row*AKV + seg)*4,
                  Vg + (size_t)row*NHW + mm0 + seg);
        }
    };

    // prologue: Q tile (256 x 64) + K0 + V0
    #pragma unroll
    for (int it=0; it<16; it++){
        int i = tid + it*256;
        int row = i >> 4, seg = (i & 15)*4;
        cpa16(sQa + (uint32_t)(row*AKV + seg)*4, Qg + (size_t)row*HD + seg);
    }
    issueK(0, sK[0]);
    issueV(0, sV[0]);
    CP_COMMIT();
    CP_WAIT0();
    __syncthreads();

    const int rowA = (lane&7) + ((lane>>3)&1)*8;
    const int colA = ((lane>>4)&1)*4;
    const int rowB = (lane&7) + ((lane>>4)&1)*8;
    const int colB = ((lane>>3)&1)*4;
    const uint32_t aQ = sQa + ((qrow + rowA)*AKV + colA)*4;
    const uint32_t aP = sPa + ((qrow + rowA)*AKV + colA)*4;
    const uint32_t bOffP = (uint32_t)(rowB*AKV + colB)*4;

    float mr[4], lr[4];
    #pragma unroll
    for (int i=0;i<4;i++){ mr[i]=-1e30f; lr[i]=0.f; }
    float o[2][8][4];
    #pragma unroll
    for (int g=0;g<2;g++)
        #pragma unroll
        for (int i=0;i<8;i++){ o[g][i][0]=0.f; o[g][i][1]=0.f; o[g][i][2]=0.f; o[g][i][3]=0.f; }

    const int r0 = qrow + (lane>>2);
    const int pcol = (lane&3)*2;

    for (int t = 0; t < 16; t++){
        if (t < 15){
            issueK((t+1)*64, sK[(t+1)&1]);
            issueV((t+1)*64, sV[(t+1)&1]);
            CP_COMMIT();
        }
        const uint32_t bK = sK[t&1] + bOffP;

        // ---- S = Q K^T (32q x 64m) ----
        float s[2][8][4];
        #pragma unroll
        for (int g=0;g<2;g++)
            #pragma unroll
            for (int i=0;i<8;i++){ s[g][i][0]=0.f; s[g][i][1]=0.f; s[g][i][2]=0.f; s[g][i][3]=0.f; }

        #pragma unroll
        for (int k8=0; k8<8; k8++){
            const uint32_t kb = k8*32;
            uint32_t qa0[4], qa1[4];
            ldmx4(qa0, aQ + kb);
            ldmx4(qa1, aQ + 16*AKV*4 + kb);
            #pragma unroll
            for (int p=0; p<4; p++){
                uint32_t k4[4];
                ldmx4(k4, bK + p*(16*AKV*4) + kb);
                mma1688(s[0][2*p],   qa0, &k4[0]);
                mma1688(s[0][2*p+1], qa0, &k4[2]);
                mma1688(s[1][2*p],   qa1, &k4[0]);
                mma1688(s[1][2*p+1], qa1, &k4[2]);
            }
        }

        // ---- online softmax: 4 row-groups (g, half) ----
        #pragma unroll
        for (int g=0; g<2; g++){
            const int rg = r0 + g*16;
            {   // half 0: regs [0..1], row rg
                float mx = -1e30f;
                #pragma unroll
                for (int nt=0; nt<8; nt++) mx = fmaxf(mx, fmaxf(s[g][nt][0], s[g][nt][1]));
                mx = fmaxf(mx, __shfl_xor_sync(0xffffffffu, mx, 1));
                mx = fmaxf(mx, __shfl_xor_sync(0xffffffffu, mx, 2));
                float mn = fmaxf(mr[2*g], mx);
                float corr = __expf(mr[2*g] - mn);
                mr[2*g] = mn;
                float sum = 0.f;
                #pragma unroll
                for (int nt=0; nt<8; nt++){
                    float p0 = __expf(s[g][nt][0]-mn), p1 = __expf(s[g][nt][1]-mn);
                    sum += p0+p1;
                    *(float2*)&sP[rg*AKV + nt*8 + pcol] = make_float2(rtf(p0), rtf(p1));
                }
                sum += __shfl_xor_sync(0xffffffffu, sum, 1);
                sum += __shfl_xor_sync(0xffffffffu, sum, 2);
                lr[2*g] = lr[2*g]*corr + sum;
                #pragma unroll
                for (int i=0;i<8;i++){ o[g][i][0]*=corr; o[g][i][1]*=corr; }
            }
            {   // half 1: regs [2..3], row rg+8
                float mx = -1e30f;
                #pragma unroll
                for (int nt=0; nt<8; nt++) mx = fmaxf(mx, fmaxf(s[g][nt][2], s[g][nt][3]));
                mx = fmaxf(mx, __shfl_xor_sync(0xffffffffu, mx, 1));
                mx = fmaxf(mx, __shfl_xor_sync(0xffffffffu, mx, 2));
                float mn = fmaxf(mr[2*g+1], mx);
                float corr = __expf(mr[2*g+1] - mn);
                mr[2*g+1] = mn;
                float sum = 0.f;
                #pragma unroll
                for (int nt=0; nt<8; nt++){
                    float p0 = __expf(s[g][nt][2]-mn), p1 = __expf(s[g][nt][3]-mn);
                    sum += p0+p1;
                    *(float2*)&sP[(rg+8)*AKV + nt*8 + pcol] = make_float2(rtf(p0), rtf(p1));
                }
                sum += __shfl_xor_sync(0xffffffffu, sum, 1);
                sum += __shfl_xor_sync(0xffffffffu, sum, 2);
                lr[2*g+1] = lr[2*g+1]*corr + sum;
                #pragma unroll
                for (int i=0;i<8;i++){ o[g][i][2]*=corr; o[g][i][3]*=corr; }
            }
        }
        __syncwarp();                         // P rows are warp-private

        // ---- O += P V^T (32q x 64d) ----
        const uint32_t bV = sV[t&1] + bOffP;
        #pragma unroll
        for (int k8=0; k8<8; k8++){
            const uint32_t kb = k8*32;
            uint32_t pa0[4], pa1[4];
            ldmx4(pa0, aP + kb);
            ldmx4(pa1, aP + 16*AKV*4 + kb);
            #pragma unroll
            for (int p=0; p<4; p++){
                uint32_t v4[4];
                ldmx4(v4, bV + p*(16*AKV*4) + kb);
                mma1688(o[0][2*p],   pa0, &v4[0]);
                mma1688(o[0][2*p+1], pa0, &v4[2]);
                mma1688(o[1][2*p],   pa1, &v4[0]);
                mma1688(o[1][2*p+1], pa1, &v4[2]);
            }
        }
        if (t < 15) CP_WAIT0();
        __syncthreads();
    }

    // ---- normalize, write proj-B layout [z][n=q][512] ----
    float* ob = OutB + ((size_t)z*NHW + q0)*NC + h*HD;
    #pragma unroll
    for (int g=0; g<2; g++){
        const int rg = r0 + g*16;
        float inv0 = 1.f/lr[2*g], inv1 = 1.f/lr[2*g+1];
        #pragma unroll
        for (int nt=0; nt<8; nt++){
            int d = nt*8 + pcol;
            *(float2*)&ob[(size_t)rg*NC + d] =
                make_float2(rtf(o[g][nt][0]*inv0), rtf(o[g][nt][1]*inv0));
            *(float2*)&ob[(size_t)(rg+8)*NC + d] =
                make_float2(rtf(o[g][nt][2]*inv1), rtf(o[g][nt][3]*inv1));
        }
    }
}

// ============================================================================
extern "C" void kernel_launch(void* const* d_in, const int* in_sizes, int n_in,
                              void* d_out, int out_size)
{
    const float* x      = (const float*)d_in[0];
    const float* gn_w   = (const float*)d_in[1];
    const float* gn_b   = (const float*)d_in[2];
    const float* qkv_w  = (const float*)d_in[3];
    const float* qkv_b  = (const float*)d_in[4];
    const float* proj_w = (const float*)d_in[5];
    const float* proj_b = (const float*)d_in[6];
    float* out = (float*)d_out;

    float *qkv, *attB, *wAf, *wPf, *xnT, *QT, *KT;
    cudaGetSymbolAddress((void**)&qkv,  g_qkv);
    cudaGetSymbolAddress((void**)&attB, g_attB);
    cudaGetSymbolAddress((void**)&wAf,  g_wAf);
    cudaGetSymbolAddress((void**)&wPf,  g_wPf);
    cudaGetSymbolAddress((void**)&xnT,  g_xnT);
    cudaGetSymbolAddress((void**)&QT,   g_QT);
    cudaGetSymbolAddress((void**)&KT,   g_KT);

    static int attr_set = 0;
    if (!attr_set){
        cudaFuncSetAttribute(attn_mma_kernel,
            cudaFuncAttributeMaxDynamicSharedMemorySize, ATT_SMEM);
        cudaFuncSetAttribute(mma_gemm_kernel,
            cudaFuncAttributeMaxDynamicSharedMemorySize, GEMM_SMEM);
        attr_set = 1;
    }

    // 1. GroupNorm stats
    gn_stats_kernel<<<NB*NG, 256>>>(x);

    // 2. qkv weights -> tf32; fused GN-apply + transpose of x
    conv_w_kernel<<<(3*NC*NC)/1024, 256>>>(qkv_w, wAf, 3*NC*NC);
    conv_xnT_kernel<<<dim3(32, 16, NB), dim3(32,8)>>>(x, gn_w, gn_b, xnT);

    // 3. QKV GEMM (tf32, 2 CTA/SM)
    mma_gemm_kernel<<<dim3(8, 12, NB), 256, GEMM_SMEM>>>(wAf, xnT, qkv_b,
                                                         nullptr, qkv, 3*NC);

    // 4. Q (scaled) + K transposes; V consumed in native layout
    conv_qkT_kernel<<<dim3(32, 2, 2*NB*NH), dim3(32,8)>>>(qkv, QT, KT);

    // 5. TF32 flash attention v2 (32q warps) -> attB (proj-B layout)
    attn_mma_kernel<<<dim3(NHW/256, NB*NH), 256, ATT_SMEM>>>(QT, KT, qkv, attB);

    // 6. proj weights; proj GEMM + residual -> out
    conv_w_kernel<<<(NC*NC)/1024, 256>>>(proj_w, wPf, NC*NC);
    mma_gemm_kernel<<<dim3(8, 4, NB), 256, GEMM_SMEM>>>(wPf, attB, proj_b,
                                                        x, out, NC);
}

// round 15
// speedup vs baseline: 2.2359x; 1.5766x over previous
#include <cuda_runtime.h>
#include <cuda_fp16.h>
#include <cstdint>

#define NB   8
#define NC   512
#define NHW  1024
#define NH   8
#define HD   64
#define NG   32
#define CPG  16

// -------- scratch (static device arrays; no cudaMalloc allowed) --------
__device__ float  g_qkv [NB*3*NC*NHW];          // 48 MB qkv activations fp32
__device__ __half g_attB[NB*NHW*NC];            //  8 MB attn out, proj-B layout [z][n][512]
__device__ float  g_mu[NB*NG], g_rs[NB*NG];     // groupnorm stats
__device__ __half g_wAf[3*NC*NC];               // 1.5 MB qkv_w  fp16 [1536][512]
__device__ __half g_wPf[NC*NC];                 // 0.5 MB proj_w fp16 [512][512]
__device__ __half g_xnT[NB*NHW*NC];             //  8 MB xn^T fp16 [z][1024][512]
__device__ __half g_QT [NB*NH*NHW*HD];          //  8 MB Q^T/8 fp16 [bh][1024][64]
__device__ __half g_KT [NB*NH*NHW*HD];          //  8 MB K^T   fp16 [bh][1024][64]
__device__ __half g_vc [NB*NH*HD*NHW];          //  8 MB V fp16 [bh][64 d][1024 m]

// -------- helpers --------
__device__ __forceinline__ uint32_t smem_u32(const void* p){
    uint32_t a;
    asm("{ .reg .u64 t; cvta.to.shared.u64 t, %1; cvt.u32.u64 %0, t; }"
        : "=r"(a) : "l"(p));
    return a;
}
__device__ __forceinline__ void ldmx4(uint32_t* r, uint32_t addr){
    asm volatile("ldmatrix.sync.aligned.m8n8.x4.shared.b16 {%0,%1,%2,%3}, [%4];"
        : "=r"(r[0]),"=r"(r[1]),"=r"(r[2]),"=r"(r[3]) : "r"(addr));
}
__device__ __forceinline__ void mmah(float* d, const uint32_t* a, const uint32_t* b){
    asm volatile("mma.sync.aligned.m16n8k16.row.col.f32.f16.f16.f32 "
        "{%0,%1,%2,%3}, {%4,%5,%6,%7}, {%8,%9}, {%0,%1,%2,%3};"
        : "+f"(d[0]),"+f"(d[1]),"+f"(d[2]),"+f"(d[3])
        : "r"(a[0]),"r"(a[1]),"r"(a[2]),"r"(a[3]), "r"(b[0]),"r"(b[1]));
}
__device__ __forceinline__ void cpa16(uint32_t s, const void* g){
    asm volatile("cp.async.cg.shared.global [%0], [%1], 16;" :: "r"(s), "l"(g));
}
#define CP_COMMIT() asm volatile("cp.async.commit_group;" ::: "memory")
#define CP_WAIT0()  asm volatile("cp.async.wait_group 0;" ::: "memory")

// ============================================================================
// GroupNorm stats (validated)
// ============================================================================
__global__ void __launch_bounds__(256)
gn_stats_kernel(const float* __restrict__ x)
{
    const int GSZ4 = CPG*NHW/4;
    int bg = blockIdx.x;
    const float4* xp = (const float4*)(x + (size_t)bg*CPG*NHW);

    float s = 0.f, s2 = 0.f;
    for (int i = threadIdx.x; i < GSZ4; i += 256){
        float4 v = xp[i];
        s  += (v.x+v.y)+(v.z+v.w);
        s2 += (v.x*v.x+v.y*v.y)+(v.z*v.z+v.w*v.w);
    }
    #pragma unroll
    for (int m=16;m;m>>=1){
        s  += __shfl_xor_sync(0xffffffffu, s,  m);
        s2 += __shfl_xor_sync(0xffffffffu, s2, m);
    }
    __shared__ float shA[8], shB[8];
    int w = threadIdx.x>>5, l = threadIdx.x&31;
    if (l==0){ shA[w]=s; shB[w]=s2; }
    __syncthreads();
    if (threadIdx.x==0){
        float S=0.f, S2=0.f;
        #pragma unroll
        for (int i=0;i<8;i++){ S+=shA[i]; S2+=shB[i]; }
        const float inv = 1.f/(float)(CPG*NHW);
        float mu  = S*inv;
        float var = S2*inv - mu*mu;
        g_mu[bg] = mu;
        g_rs[bg] = rsqrtf(var + 1e-5f);
    }
}

// ============================================================================
// Weight converter: fp32 -> fp16
// ============================================================================
__global__ void __launch_bounds__(256)
conv_w_kernel(const float* __restrict__ w, __half* __restrict__ o, int total)
{
    int i = (blockIdx.x*256 + threadIdx.x)*4;
    if (i >= total) return;
    float4 v = *(const float4*)(w + i);
    __half2 h0 = __floats2half2_rn(v.x, v.y);
    __half2 h1 = __floats2half2_rn(v.z, v.w);
    *(__half2*)(o + i)     = h0;
    *(__half2*)(o + i + 2) = h1;
}

// ============================================================================
// Fused GroupNorm-apply + transpose: x [z][512][1024] -> fp16 [z][1024 n][512 k]
// ============================================================================
__global__ void __launch_bounds__(256)
conv_xnT_kernel(const float* __restrict__ x,
                const float* __restrict__ gw,
                const float* __restrict__ gb,
                __half* __restrict__ out)
{
    __shared__ float t[32][33];
    int n0 = blockIdx.x*32, k0 = blockIdx.y*32, z = blockIdx.z;
    int tx = threadIdx.x, ty = threadIdx.y;
    const float* ip = x + ((size_t)z*NC + k0)*NHW + n0;
    #pragma unroll
    for (int j=0;j<4;j++)
        t[ty*4+j][tx] = ip[(size_t)(ty*4+j)*NHW + tx];
    __syncthreads();
    const int c = k0 + tx;
    const int g = c >> 4;
    float mu = g_mu[z*NG+g], rs = g_rs[z*NG+g];
    float a = gw[c]*rs, off = gb[c] - mu*a;
    __half* op = out + ((size_t)z*NHW + n0)*NC + k0;
    #pragma unroll
    for (int j=0;j<4;j++){
        int nl = ty*4+j;
        op[(size_t)nl*NC + tx] = __float2half_rn(t[tx][nl]*a + off);
    }
}

// ============================================================================
// Q+K transpose: z<64 -> Q (scale 1/8), z>=64 -> K. out fp16 [bh][1024 n][64 d]
// ============================================================================
__global__ void __launch_bounds__(256)
conv_qkT_kernel(const float* __restrict__ in,
                __half* __restrict__ outQ,
                __half* __restrict__ outK)
{
    __shared__ float t[32][33];
    int zz = blockIdx.z;
    int isK = zz >= NB*NH;
    int bh = zz & 63;
    int b = bh >> 3, h = bh & 7;
    int coff  = isK ? NC : 0;
    float scale = isK ? 1.0f : 0.125f;
    __half* out = isK ? outK : outQ;

    int n0 = blockIdx.x*32, d0 = blockIdx.y*32;
    int tx = threadIdx.x, ty = threadIdx.y;
    const float* ip = in + ((size_t)b*3*NC + coff + h*HD + d0)*NHW + n0;
    #pragma unroll
    for (int j=0;j<4;j++)
        t[ty*4+j][tx] = ip[(size_t)(ty*4+j)*NHW + tx];
    __syncthreads();
    __half* op = out + ((size_t)bh*NHW + n0)*HD + d0;
    #pragma unroll
    for (int j=0;j<4;j++){
        int nl = ty*4+j;
        op[(size_t)nl*HD + tx] = __float2half_rn(t[tx][nl]*scale);
    }
}

// ============================================================================
// V converter: g_qkv V part -> fp16 [bh][64 d][1024 m]
// ============================================================================
__global__ void __launch_bounds__(256)
conv_v_kernel(const float* __restrict__ in, __half* __restrict__ out)
{
    int bh = blockIdx.y, b = bh >> 3, h = bh & 7;
    int idx = (blockIdx.x*256 + threadIdx.x)*4;
    int d = idx >> 10, m = idx & 1023;
    float4 v = *(const float4*)(in + ((size_t)b*3*NC + 2*NC + h*HD + d)*NHW + m);
    __half* o = out + (size_t)bh*HD*NHW + (size_t)d*NHW + m;
    *(__half2*)(o)     = __floats2half2_rn(v.x, v.y);
    *(__half2*)(o + 2) = __floats2half2_rn(v.z, v.w);
}

// ============================================================================
// FP16 GEMM: C[z][m][n] = A[m][:512] * B[z][n][:512]^T + bias[m] (+ res)
// 128x128 tile, K-chunks of 64, 2-stage cp.async, 2 CTAs/SM.
// ============================================================================
#define TPAD 72                         // halfs per smem row (144 B)
#define GTE (128*TPAD)                  // halfs per tile
#define GSTAGE_B (2*GTE*2)              // bytes per stage (A+B) = 36864
#define GEMM_SMEM (2*GSTAGE_B)          // 73728 B -> 2 CTAs/SM

__global__ void __launch_bounds__(256,2)
mma_gemm_kernel(const __half* __restrict__ A2,
                const __half* __restrict__ B2t,
                const float* __restrict__ bias,
                const float* __restrict__ res,
                float* __restrict__ C,
                int M)
{
    extern __shared__ __half smh[];
    const int tid  = threadIdx.x;
    const int warp = tid >> 5, lane = tid & 31;
    const int wm = warp >> 2, wn = warp & 3;
    const int n0 = blockIdx.x*128, m0 = blockIdx.y*128, z = blockIdx.z;

    const __half* Ag = A2 + (size_t)m0*NC;
    const __half* Bg = B2t + ((size_t)z*NHW + n0)*NC;

    const uint32_t smBase = smem_u32(smh);
    const uint32_t aBase = smBase +
        ((wm*64 + (lane&15))*TPAD + (lane>>4)*8)*2;
    const uint32_t bBase = smBase + GTE*2 +
        ((wn*32 + (lane&7) + ((lane>>4)&1)*8)*TPAD + ((lane>>3)&1)*8)*2;

    auto issue_chunk = [&](int c){
        const uint32_t base = smBase + (c & 1)*GSTAGE_B;
        const int kh = c*64;
        #pragma unroll
        for (int it=0; it<4; it++){
            int i = tid + it*256;
            int row = i >> 3, seg = (i & 7)*8;
            cpa16(base + (uint32_t)(row*TPAD + seg)*2,
                  Ag + (size_t)row*NC + kh + seg);
            cpa16(base + GTE*2 + (uint32_t)(row*TPAD + seg)*2,
                  Bg + (size_t)row*NC + kh + seg);
        }
        CP_COMMIT();
    };

    float acc[4][4][4];
    #pragma unroll
    for (int i=0;i<4;i++)
        #pragma unroll
        for (int j=0;j<4;j++)
            #pragma unroll
            for (int r=0;r<4;r++) acc[i][j][r]=0.f;

    issue_chunk(0);

    for (int c = 0; c < 8; c++){
        CP_WAIT0();
        __syncthreads();
        if (c < 7) issue_chunk(c+1);

        const uint32_t so = (c & 1)*GSTAGE_B;
        #pragma unroll
        for (int k16 = 0; k16 < 4; k16++){
            const uint32_t kb = k16*32;            // 16 halfs = 32 B
            uint32_t b4[2][4];
            ldmx4(b4[0], bBase + so + kb);
            ldmx4(b4[1], bBase + so + 16*TPAD*2 + kb);
            #pragma unroll
            for (int mt=0; mt<4; mt++){
                uint32_t a4[4];
                ldmx4(a4, aBase + so + mt*(16*TPAD*2) + kb);
                mmah(acc[mt][0], a4, &b4[0][0]);
                mmah(acc[mt][1], a4, &b4[0][2]);
                mmah(acc[mt][2], a4, &b4[1][0]);
                mmah(acc[mt][3], a4, &b4[1][2]);
            }
        }
    }

    const int rBase = m0 + wm*64 + (lane >> 2);
    const int cBase = n0 + wn*32 + (lane & 3)*2;
    #pragma unroll
    for (int mt=0; mt<4; mt++){
        const int r0 = rBase + mt*16;
        const float bi0 = bias[r0], bi1 = bias[r0+8];
        float* cp0 = C + ((size_t)z*M + r0  )*NHW;
        float* cp1 = C + ((size_t)z*M + r0+8)*NHW;
        const float* rp0 = res ? res + ((size_t)z*M + r0  )*NHW : nullptr;
        const float* rp1 = res ? res + ((size_t)z*M + r0+8)*NHW : nullptr;
        #pragma unroll
        for (int nt=0; nt<4; nt++){
            const int cc = cBase + nt*8;
            float2 v0 = make_float2(acc[mt][nt][0]+bi0, acc[mt][nt][1]+bi0);
            float2 v1 = make_float2(acc[mt][nt][2]+bi1, acc[mt][nt][3]+bi1);
            if (rp0){
                float2 a0 = *(const float2*)(rp0 + cc);
                float2 a1 = *(const float2*)(rp1 + cc);
                v0.x+=a0.x; v0.y+=a0.y; v1.x+=a1.x; v1.y+=a1.y;
            }
            *(float2*)(cp0 + cc) = v0;
            *(float2*)(cp1 + cc) = v1;
        }
    }
}

// ============================================================================
// FP16 flash attention: 512 threads, 16 warps x 16q, q-tile 256, m-tile 64,
// double-buffered K/V cp.async, Q cached in register A-frags, P fp16 staged
// in the Q smem region. 1 CTA/SM (reg-limited).
// smem: K[2] + V[2] (64x72 h) + P/Q (256x72 h) = 73728 B.
// ============================================================================
#define AKV 72
#define KTEh (64*AKV)                   // 4608 halfs
#define OFF_Vh (2*KTEh)
#define OFF_Ph (4*KTEh)                 // 18432 halfs
#define ATT_SMEM ((OFF_Ph + 256*AKV)*2) // 73728 B

__global__ void __launch_bounds__(512,1)
attn_mma_kernel(const __half* __restrict__ QT,
                const __half* __restrict__ KT,
                const __half* __restrict__ Vc,
                __half* __restrict__ OutB)
{
    extern __shared__ __half smh[];
    const int tid = threadIdx.x, warp = tid >> 5, lane = tid & 31;
    const int q0 = blockIdx.x*256, bh = blockIdx.y;
    const int z = bh >> 3, h = bh & 7;
    const int qrow = warp*16;

    const __half* Qg = QT + ((size_t)bh*NHW + q0)*HD;
    const __half* Kg = KT + (size_t)bh*NHW*HD;
    const __half* Vg = Vc + (size_t)bh*HD*NHW;

    const uint32_t smBase = smem_u32(smh);
    const uint32_t sK[2] = { smBase, smBase + KTEh*2 };
    const uint32_t sV[2] = { smBase + OFF_Vh*2, smBase + (OFF_Vh+KTEh)*2 };
    __half* sP = smh + OFF_Ph;
    const uint32_t sPa = smBase + OFF_Ph*2;

    auto issueK = [&](int mm0, uint32_t dst){
        int row = tid >> 3, seg = (tid & 7)*8;    // 512 thr = 64 rows x 8 segs
        cpa16(dst + (uint32_t)(row*AKV + seg)*2,
              Kg + (size_t)(mm0+row)*HD + seg);
    };
    auto issueV = [&](int mm0, uint32_t dst){
        int row = tid >> 3, seg = (tid & 7)*8;
        cpa16(dst + (uint32_t)(row*AKV + seg)*2,
              Vg + (size_t)row*NHW + mm0 + seg);
    };

    // prologue: Q tile (256 x 64 h) into P region; K0,V0
    #pragma unroll
    for (int it=0; it<4; it++){
        int i = tid + it*512;
        int row = i >> 3, seg = (i & 7)*8;
        cpa16(sPa + (uint32_t)(row*AKV + seg)*2, Qg + (size_t)row*HD + seg);
    }
    issueK(0, sK[0]);
    issueV(0, sV[0]);
    CP_COMMIT();
    CP_WAIT0();
    __syncthreads();

    const uint32_t aQP = sPa + ((qrow + (lane&15))*AKV + (lane>>4)*8)*2;
    const uint32_t bOffP = (((lane&7) + ((lane>>4)&1)*8)*AKV + ((lane>>3)&1)*8)*2;

    // Q fragments in registers (4 k16 steps over d=64)
    uint32_t qf[4][4];
    #pragma unroll
    for (int k=0; k<4; k++) ldmx4(qf[k], aQP + k*32);

    float m0r = -1e30f, m1r = -1e30f, l0r = 0.f, l1r = 0.f;
    float o[8][4];
    #pragma unroll
    for (int i=0;i<8;i++){ o[i][0]=0.f; o[i][1]=0.f; o[i][2]=0.f; o[i][3]=0.f; }

    const int r0 = qrow + (lane>>2);
    const int pcol = (lane&3)*2;

    for (int t = 0; t < 16; t++){
        if (t < 15){
            issueK((t+1)*64, sK[(t+1)&1]);
            issueV((t+1)*64, sV[(t+1)&1]);
            CP_COMMIT();
        }
        const uint32_t bK = sK[t&1] + bOffP;

        // ---- S = Q K^T (16q x 64m) ----
        float s[8][4];
        #pragma unroll
        for (int i=0;i<8;i++){ s[i][0]=0.f; s[i][1]=0.f; s[i][2]=0.f; s[i][3]=0.f; }

        #pragma unroll
        for (int k16=0; k16<4; k16++){
            const uint32_t kb = k16*32;
            #pragma unroll
            for (int p=0; p<4; p++){
                uint32_t k4[4];
                ldmx4(k4, bK + p*(16*AKV*2) + kb);
                mmah(s[2*p],   qf[k16], &k4[0]);
                mmah(s[2*p+1], qf[k16], &k4[2]);
            }
        }

        // ---- online softmax (warp-local rows r0, r0+8); P stored fp16 ----
        {
            float mx = -1e30f;
            #pragma unroll
            for (int nt=0; nt<8; nt++) mx = fmaxf(mx, fmaxf(s[nt][0], s[nt][1]));
            mx = fmaxf(mx, __shfl_xor_sync(0xffffffffu, mx, 1));
            mx = fmaxf(mx, __shfl_xor_sync(0xffffffffu, mx, 2));
            float mn = fmaxf(m0r, mx);
            float corr = __expf(m0r - mn);
            m0r = mn;
            float sum = 0.f;
            #pragma unroll
            for (int nt=0; nt<8; nt++){
                float p0 = __expf(s[nt][0]-mn), p1 = __expf(s[nt][1]-mn);
                sum += p0+p1;
                *(__half2*)&sP[r0*AKV + nt*8 + pcol] = __floats2half2_rn(p0, p1);
            }
            sum += __shfl_xor_sync(0xffffffffu, sum, 1);
            sum += __shfl_xor_sync(0xffffffffu, sum, 2);
            l0r = l0r*corr + sum;
            #pragma unroll
            for (int i=0;i<8;i++){ o[i][0]*=corr; o[i][1]*=corr; }
        }
        {
            float mx = -1e30f;
            #pragma unroll
            for (int nt=0; nt<8; nt++) mx = fmaxf(mx, fmaxf(s[nt][2], s[nt][3]));
            mx = fmaxf(mx, __shfl_xor_sync(0xffffffffu, mx, 1));
            mx = fmaxf(mx, __shfl_xor_sync(0xffffffffu, mx, 2));
            float mn = fmaxf(m1r, mx);
            float corr = __expf(m1r - mn);
            m1r = mn;
            float sum = 0.f;
            #pragma unroll
            for (int nt=0; nt<8; nt++){
                float p0 = __expf(s[nt][2]-mn), p1 = __expf(s[nt][3]-mn);
                sum += p0+p1;
                *(__half2*)&sP[(r0+8)*AKV + nt*8 + pcol] = __floats2half2_rn(p0, p1);
            }
            sum += __shfl_xor_sync(0xffffffffu, sum, 1);
            sum += __shfl_xor_sync(0xffffffffu, sum, 2);
            l1r = l1r*corr + sum;
            #pragma unroll
            for (int i=0;i<8;i++){ o[i][2]*=corr; o[i][3]*=corr; }
        }
        __syncwarp();                         // P rows are warp-private

        // ---- O += P V^T (16q x 64d, k = m 64) ----
        const uint32_t bV = sV[t&1] + bOffP;
        #pragma unroll
        for (int k16=0; k16<4; k16++){
            const uint32_t kb = k16*32;
            uint32_t pa[4];
            ldmx4(pa, aQP + kb);
            #pragma unroll
            for (int p=0; p<4; p++){
                uint32_t v4[4];
                ldmx4(v4, bV + p*(16*AKV*2) + kb);
                mmah(o[2*p],   pa, &v4[0]);
                mmah(o[2*p+1], pa, &v4[2]);
            }
        }
        if (t < 15) CP_WAIT0();
        __syncthreads();
    }

    // ---- normalize, write proj-B fp16 layout [z][n=q][512] ----
    float inv0 = 1.f/l0r, inv1 = 1.f/l1r;
    __half* ob = OutB + ((size_t)z*NHW + q0)*NC + h*HD;
    #pragma unroll
    for (int nt=0; nt<8; nt++){
        int d = nt*8 + pcol;
        *(__half2*)&ob[(size_t)r0*NC + d] =
            __floats2half2_rn(o[nt][0]*inv0, o[nt][1]*inv0);
        *(__half2*)&ob[(size_t)(r0+8)*NC + d] =
            __floats2half2_rn(o[nt][2]*inv1, o[nt][3]*inv1);
    }
}

// ============================================================================
extern "C" void kernel_launch(void* const* d_in, const int* in_sizes, int n_in,
                              void* d_out, int out_size)
{
    const float* x      = (const float*)d_in[0];
    const float* gn_w   = (const float*)d_in[1];
    const float* gn_b   = (const float*)d_in[2];
    const float* qkv_w  = (const float*)d_in[3];
    const float* qkv_b  = (const float*)d_in[4];
    const float* proj_w = (const float*)d_in[5];
    const float* proj_b = (const float*)d_in[6];
    float* out = (float*)d_out;

    float *qkv;
    __half *attB, *wAf, *wPf, *xnT, *QT, *KT, *vc;
    cudaGetSymbolAddress((void**)&qkv,  g_qkv);
    cudaGetSymbolAddress((void**)&attB, g_attB);
    cudaGetSymbolAddress((void**)&wAf,  g_wAf);
    cudaGetSymbolAddress((void**)&wPf,  g_wPf);
    cudaGetSymbolAddress((void**)&xnT,  g_xnT);
    cudaGetSymbolAddress((void**)&QT,   g_QT);
    cudaGetSymbolAddress((void**)&KT,   g_KT);
    cudaGetSymbolAddress((void**)&vc,   g_vc);

    static int attr_set = 0;
    if (!attr_set){
        cudaFuncSetAttribute(attn_mma_kernel,
            cudaFuncAttributeMaxDynamicSharedMemorySize, ATT_SMEM);
        cudaFuncSetAttribute(mma_gemm_kernel,
            cudaFuncAttributeMaxDynamicSharedMemorySize, GEMM_SMEM);
        attr_set = 1;
    }

    // 1. GroupNorm stats
    gn_stats_kernel<<<NB*NG, 256>>>(x);

    // 2. Weights -> fp16; fused GN-apply + transpose of x -> fp16
    conv_w_kernel<<<(3*NC*NC)/1024, 256>>>(qkv_w, wAf, 3*NC*NC);
    conv_xnT_kernel<<<dim3(32, 16, NB), dim3(32,8)>>>(x, gn_w, gn_b, xnT);

    // 3. QKV GEMM (fp16 HMMA, 2 CTA/SM) -> g_qkv fp32
    mma_gemm_kernel<<<dim3(8, 12, NB), 256, GEMM_SMEM>>>(wAf, xnT, qkv_b,
                                                         nullptr, qkv, 3*NC);

    // 4. Q (scaled) + K transposes -> fp16; V -> fp16 planes
    conv_qkT_kernel<<<dim3(32, 2, 2*NB*NH), dim3(32,8)>>>(qkv, QT, KT);
    conv_v_kernel<<<dim3(64, NB*NH), 256>>>(qkv, vc);

    // 5. FP16 flash attention -> attB (proj-B fp16 layout)
    attn_mma_kernel<<<dim3(NHW/256, NB*NH), 512, ATT_SMEM>>>(QT, KT, vc, attB);

    // 6. proj weights -> fp16; proj GEMM + residual -> out
    conv_w_kernel<<<(NC*NC)/1024, 256>>>(proj_w, wPf, NC*NC);
    mma_gemm_kernel<<<dim3(8, 4, NB), 256, GEMM_SMEM>>>(wPf, attB, proj_b,
                                                        x, out, NC);
}

// round 17
// speedup vs baseline: 2.3126x; 1.0343x over previous
#include <cuda_runtime.h>
#include <cuda_fp16.h>
#include <cstdint>

#define NB   8
#define NC   512
#define NHW  1024
#define NH   8
#define HD   64
#define NG   32
#define CPG  16

// -------- scratch (static device arrays; no cudaMalloc allowed) --------
__device__ __half g_attB[NB*NHW*NC];            //  8 MB attn out, proj-B layout [z][n][512]
__device__ float  g_mu[NB*NG], g_rs[NB*NG];     // groupnorm stats
__device__ __half g_wAf[3*NC*NC];               // 1.5 MB qkv_w  fp16 [1536][512]
__device__ __half g_wPf[NC*NC];                 // 0.5 MB proj_w fp16 [512][512]
__device__ __half g_xnT[NB*NHW*NC];             //  8 MB xn^T fp16 [z][1024][512]
__device__ __half g_QT [NB*NH*NHW*HD];          //  8 MB Q^T/8 fp16 [bh][1024][64]
__device__ __half g_KT [NB*NH*NHW*HD];          //  8 MB K^T   fp16 [bh][1024][64]
__device__ __half g_vc [NB*NH*HD*NHW];          //  8 MB V fp16 [bh][64 d][1024 m]

// -------- helpers --------
__device__ __forceinline__ uint32_t smem_u32(const void* p){
    uint32_t a;
    asm("{ .reg .u64 t; cvta.to.shared.u64 t, %1; cvt.u32.u64 %0, t; }"
        : "=r"(a) : "l"(p));
    return a;
}
__device__ __forceinline__ void ldmx4(uint32_t* r, uint32_t addr){
    asm volatile("ldmatrix.sync.aligned.m8n8.x4.shared.b16 {%0,%1,%2,%3}, [%4];"
        : "=r"(r[0]),"=r"(r[1]),"=r"(r[2]),"=r"(r[3]) : "r"(addr));
}
__device__ __forceinline__ void mmah(float* d, const uint32_t* a, const uint32_t* b){
    asm volatile("mma.sync.aligned.m16n8k16.row.col.f32.f16.f16.f32 "
        "{%0,%1,%2,%3}, {%4,%5,%6,%7}, {%8,%9}, {%0,%1,%2,%3};"
        : "+f"(d[0]),"+f"(d[1]),"+f"(d[2]),"+f"(d[3])
        : "r"(a[0]),"r"(a[1]),"r"(a[2]),"r"(a[3]), "r"(b[0]),"r"(b[1]));
}
__device__ __forceinline__ void cpa16(uint32_t s, const void* g){
    asm volatile("cp.async.cg.shared.global [%0], [%1], 16;" :: "r"(s), "l"(g));
}
#define CP_COMMIT() asm volatile("cp.async.commit_group;" ::: "memory")
#define CP_WAIT0()  asm volatile("cp.async.wait_group 0;" ::: "memory")

// ============================================================================
// GroupNorm stats (validated)
// ============================================================================
__global__ void __launch_bounds__(256)
gn_stats_kernel(const float* __restrict__ x)
{
    const int GSZ4 = CPG*NHW/4;
    int bg = blockIdx.x;
    const float4* xp = (const float4*)(x + (size_t)bg*CPG*NHW);

    float s = 0.f, s2 = 0.f;
    for (int i = threadIdx.x; i < GSZ4; i += 256){
        float4 v = xp[i];
        s  += (v.x+v.y)+(v.z+v.w);
        s2 += (v.x*v.x+v.y*v.y)+(v.z*v.z+v.w*v.w);
    }
    #pragma unroll
    for (int m=16;m;m>>=1){
        s  += __shfl_xor_sync(0xffffffffu, s,  m);
        s2 += __shfl_xor_sync(0xffffffffu, s2, m);
    }
    __shared__ float shA[8], shB[8];
    int w = threadIdx.x>>5, l = threadIdx.x&31;
    if (l==0){ shA[w]=s; shB[w]=s2; }
    __syncthreads();
    if (threadIdx.x==0){
        float S=0.f, S2=0.f;
        #pragma unroll
        for (int i=0;i<8;i++){ S+=shA[i]; S2+=shB[i]; }
        const float inv = 1.f/(float)(CPG*NHW);
        float mu  = S*inv;
        float var = S2*inv - mu*mu;
        g_mu[bg] = mu;
        g_rs[bg] = rsqrtf(var + 1e-5f);
    }
}

// ============================================================================
// Weight converter: fp32 -> fp16
// ============================================================================
__global__ void __launch_bounds__(256)
conv_w_kernel(const float* __restrict__ w, __half* __restrict__ o, int total)
{
    int i = (blockIdx.x*256 + threadIdx.x)*4;
    if (i >= total) return;
    float4 v = *(const float4*)(w + i);
    *(__half2*)(o + i)     = __floats2half2_rn(v.x, v.y);
    *(__half2*)(o + i + 2) = __floats2half2_rn(v.z, v.w);
}

// ============================================================================
// Fused GroupNorm-apply + transpose: x [z][512][1024] -> fp16 [z][1024 n][512 k]
// ============================================================================
__global__ void __launch_bounds__(256)
conv_xnT_kernel(const float* __restrict__ x,
                const float* __restrict__ gw,
                const float* __restrict__ gb,
                __half* __restrict__ out)
{
    __shared__ float t[32][33];
    int n0 = blockIdx.x*32, k0 = blockIdx.y*32, z = blockIdx.z;
    int tx = threadIdx.x, ty = threadIdx.y;
    const float* ip = x + ((size_t)z*NC + k0)*NHW + n0;
    #pragma unroll
    for (int j=0;j<4;j++)
        t[ty*4+j][tx] = ip[(size_t)(ty*4+j)*NHW + tx];
    __syncthreads();
    const int c = k0 + tx;
    const int g = c >> 4;
    float mu = g_mu[z*NG+g], rs = g_rs[z*NG+g];
    float a = gw[c]*rs, off = gb[c] - mu*a;
    __half* op = out + ((size_t)z*NHW + n0)*NC + k0;
    #pragma unroll
    for (int j=0;j<4;j++){
        int nl = ty*4+j;
        op[(size_t)nl*NC + tx] = __float2half_rn(t[tx][nl]*a + off);
    }
}

// ============================================================================
// FP16 GEMM: D[z] = A[m][:512] * B[z][n][:512]^T + bias[m]
// mode 0: fp32 C out (+res)           (proj)
// mode 1: fused QKV epilogue -> QT (q/8, [bh][n][64]), KT, Vc ([bh][d][m])
// 128x128 tile, K-chunks 64, 2-stage cp.async, 2 CTAs/SM.
// ============================================================================
#define TPAD 72
#define GTE (128*TPAD)
#define GSTAGE_B (2*GTE*2)
#define GEMM_SMEM (2*GSTAGE_B)          // 73728 B
#define CSP 136                         // epilogue stage stride (halfs)

__global__ void __launch_bounds__(256,2)
mma_gemm_kernel(const __half* __restrict__ A2,
                const __half* __restrict__ B2t,
                const float* __restrict__ bias,
                const float* __restrict__ res,
                float* __restrict__ C,
                int M, int mode,
                __half* __restrict__ QT,
                __half* __restrict__ KT,
                __half* __restrict__ Vc)
{
    extern __shared__ __half smh[];
    const int tid  = threadIdx.x;
    const int warp = tid >> 5, lane = tid & 31;
    const int wm = warp >> 2, wn = warp & 3;
    const int n0 = blockIdx.x*128, m0 = blockIdx.y*128, z = blockIdx.z;

    const __half* Ag = A2 + (size_t)m0*NC;
    const __half* Bg = B2t + ((size_t)z*NHW + n0)*NC;

    const uint32_t smBase = smem_u32(smh);
    const uint32_t aBase = smBase +
        ((wm*64 + (lane&15))*TPAD + (lane>>4)*8)*2;
    const uint32_t bBase = smBase + GTE*2 +
        ((wn*32 + (lane&7) + ((lane>>4)&1)*8)*TPAD + ((lane>>3)&1)*8)*2;

    auto issue_chunk = [&](int c){
        const uint32_t base = smBase + (c & 1)*GSTAGE_B;
        const int kh = c*64;
        #pragma unroll
        for (int it=0; it<4; it++){
            int i = tid + it*256;
            int row = i >> 3, seg = (i & 7)*8;
            cpa16(base + (uint32_t)(row*TPAD + seg)*2,
                  Ag + (size_t)row*NC + kh + seg);
            cpa16(base + GTE*2 + (uint32_t)(row*TPAD + seg)*2,
                  Bg + (size_t)row*NC + kh + seg);
        }
        CP_COMMIT();
    };

    float acc[4][4][4];
    #pragma unroll
    for (int i=0;i<4;i++)
        #pragma unroll
        for (int j=0;j<4;j++)
            #pragma unroll
            for (int r=0;r<4;r++) acc[i][j][r]=0.f;

    issue_chunk(0);

    for (int c = 0; c < 8; c++){
        CP_WAIT0();
        __syncthreads();
        if (c < 7) issue_chunk(c+1);

        const uint32_t so = (c & 1)*GSTAGE_B;
        #pragma unroll
        for (int k16 = 0; k16 < 4; k16++){
            const uint32_t kb = k16*32;
            uint32_t b4[2][4];
            ldmx4(b4[0], bBase + so + kb);
            ldmx4(b4[1], bBase + so + 16*TPAD*2 + kb);
            #pragma unroll
            for (int mt=0; mt<4; mt++){
                uint32_t a4[4];
                ldmx4(a4, aBase + so + mt*(16*TPAD*2) + kb);
                mmah(acc[mt][0], a4, &b4[0][0]);
                mmah(acc[mt][1], a4, &b4[0][2]);
                mmah(acc[mt][2], a4, &b4[1][0]);
                mmah(acc[mt][3], a4, &b4[1][2]);
            }
        }
    }

    if (mode == 0){
        const int rBase = m0 + wm*64 + (lane >> 2);
        const int cBase = n0 + wn*32 + (lane & 3)*2;
        #pragma unroll
        for (int mt=0; mt<4; mt++){
            const int r0 = rBase + mt*16;
            const float bi0 = bias[r0], bi1 = bias[r0+8];
            float* cp0 = C + ((size_t)z*M + r0  )*NHW;
            float* cp1 = C + ((size_t)z*M + r0+8)*NHW;
            const float* rp0 = res + ((size_t)z*M + r0  )*NHW;
            const float* rp1 = res + ((size_t)z*M + r0+8)*NHW;
            #pragma unroll
            for (int nt=0; nt<4; nt++){
                const int cc = cBase + nt*8;
                float2 a0 = *(const float2*)(rp0 + cc);
                float2 a1 = *(const float2*)(rp1 + cc);
                *(float2*)(cp0 + cc) =
                    make_float2(acc[mt][nt][0]+bi0+a0.x, acc[mt][nt][1]+bi0+a0.y);
                *(float2*)(cp1 + cc) =
                    make_float2(acc[mt][nt][2]+bi1+a1.x, acc[mt][nt][3]+bi1+a1.y);
            }
        }
        return;
    }

    // ---- mode 1: fused QKV epilogue ----
    __syncthreads();                          // pipeline smem now reusable
    __half* Cs = smh;                         // [128 m][CSP]
    const int kind = m0 >> 9;                 // 0=Q 1=K 2=V
    const float scale = (kind == 0) ? 0.125f : 1.f;
    const int rloc = wm*64 + (lane >> 2);
    const int cloc = wn*32 + (lane & 3)*2;
    #pragma unroll
    for (int mt=0; mt<4; mt++){
        const int r = rloc + mt*16;
        const float bi0 = bias[m0+r], bi1 = bias[m0+r+8];
        #pragma unroll
        for (int nt=0; nt<4; nt++){
            const int cc = cloc + nt*8;
            *(__half2*)&Cs[r*CSP + cc] =
                __floats2half2_rn((acc[mt][nt][0]+bi0)*scale,
                                  (acc[mt][nt][1]+bi0)*scale);
            *(__half2*)&Cs[(r+8)*CSP + cc] =
                __floats2half2_rn((acc[mt][nt][2]+bi1)*scale,
                                  (acc[mt][nt][3]+bi1)*scale);
        }
    }
    __syncthreads();

    const int mbase = m0 - kind*512;          // 0..511 within Q/K/V block
    if (kind == 2){
        // V: rows are d, columns are spatial m -> direct row copy (64 halfs)
        const int row = tid >> 1, seg = (tid & 1)*64;
        const int mg = mbase + row;
        const int head = mg >> 6, d = mg & 63;
        __half* dst = Vc + (((size_t)(z*8+head)*HD + d)*NHW) + n0 + seg;
        const __half* src = Cs + row*CSP + seg;
        #pragma unroll
        for (int j=0; j<8; j++)
            *(uint4*)(dst + j*8) = *(const uint4*)(src + j*8);
    } else {
        // Q/K: transpose -> [bh][n][64]  (64 halfs per thread)
        __half* base = (kind == 0) ? QT : KT;
        const int nloc = tid >> 1, dhalf = (tid & 1)*64;
        const int head = (mbase + dhalf) >> 6;
        __half* dst = base + ((size_t)(z*8+head)*NHW + n0 + nloc)*HD;
        __half buf[64];
        #pragma unroll
        for (int d=0; d<64; d++)
            buf[d] = Cs[(dhalf+d)*CSP + nloc];
        #pragma unroll
        for (int j=0; j<8; j++)
            *(uint4*)(dst + j*8) = *(const uint4*)(buf + j*8);
    }
}

// ============================================================================
// FP16 flash attention (validated R15): 512 thr, 16 warps x 16q, q-tile 256,
// m-tile 64, double-buffered K/V, Q cached in regs, P fp16 in Q smem region.
// ============================================================================
#define AKV 72
#define KTEh (64*AKV)
#define OFF_Vh (2*KTEh)
#define OFF_Ph (4*KTEh)
#define ATT_SMEM ((OFF_Ph + 256*AKV)*2) // 73728 B

__global__ void __launch_bounds__(512,1)
attn_mma_kernel(const __half* __restrict__ QT,
                const __half* __restrict__ KT,
                const __half* __restrict__ Vc,
                __half* __restrict__ OutB)
{
    extern __shared__ __half smh[];
    const int tid = threadIdx.x, warp = tid >> 5, lane = tid & 31;
    const int q0 = blockIdx.x*256, bh = blockIdx.y;
    const int z = bh >> 3, h = bh & 7;
    const int qrow = warp*16;

    const __half* Qg = QT + ((size_t)bh*NHW + q0)*HD;
    const __half* Kg = KT + (size_t)bh*NHW*HD;
    const __half* Vg = Vc + (size_t)bh*HD*NHW;

    const uint32_t smBase = smem_u32(smh);
    const uint32_t sK[2] = { smBase, smBase + KTEh*2 };
    const uint32_t sV[2] = { smBase + OFF_Vh*2, smBase + (OFF_Vh+KTEh)*2 };
    __half* sP = smh + OFF_Ph;
    const uint32_t sPa = smBase + OFF_Ph*2;

    auto issueK = [&](int mm0, uint32_t dst){
        int row = tid >> 3, seg = (tid & 7)*8;
        cpa16(dst + (uint32_t)(row*AKV + seg)*2,
              Kg + (size_t)(mm0+row)*HD + seg);
    };
    auto issueV = [&](int mm0, uint32_t dst){
        int row = tid >> 3, seg = (tid & 7)*8;
        cpa16(dst + (uint32_t)(row*AKV + seg)*2,
              Vg + (size_t)row*NHW + mm0 + seg);
    };

    #pragma unroll
    for (int it=0; it<4; it++){
        int i = tid + it*512;
        int row = i >> 3, seg = (i & 7)*8;
        cpa16(sPa + (uint32_t)(row*AKV + seg)*2, Qg + (size_t)row*HD + seg);
    }
    issueK(0, sK[0]);
    issueV(0, sV[0]);
    CP_COMMIT();
    CP_WAIT0();
    __syncthreads();

    const uint32_t aQP = sPa + ((qrow + (lane&15))*AKV + (lane>>4)*8)*2;
    const uint32_t bOffP = (((lane&7) + ((lane>>4)&1)*8)*AKV + ((lane>>3)&1)*8)*2;

    uint32_t qf[4][4];
    #pragma unroll
    for (int k=0; k<4; k++) ldmx4(qf[k], aQP + k*32);

    float m0r = -1e30f, m1r = -1e30f, l0r = 0.f, l1r = 0.f;
    float o[8][4];
    #pragma unroll
    for (int i=0;i<8;i++){ o[i][0]=0.f; o[i][1]=0.f; o[i][2]=0.f; o[i][3]=0.f; }

    const int r0 = qrow + (lane>>2);
    const int pcol = (lane&3)*2;

    for (int t = 0; t < 16; t++){
        if (t < 15){
            issueK((t+1)*64, sK[(t+1)&1]);
            issueV((t+1)*64, sV[(t+1)&1]);
            CP_COMMIT();
        }
        const uint32_t bK = sK[t&1] + bOffP;

        float s[8][4];
        #pragma unroll
        for (int i=0;i<8;i++){ s[i][0]=0.f; s[i][1]=0.f; s[i][2]=0.f; s[i][3]=0.f; }

        #pragma unroll
        for (int k16=0; k16<4; k16++){
            const uint32_t kb = k16*32;
            #pragma unroll
            for (int p=0; p<4; p++){
                uint32_t k4[4];
                ldmx4(k4, bK + p*(16*AKV*2) + kb);
                mmah(s[2*p],   qf[k16], &k4[0]);
                mmah(s[2*p+1], qf[k16], &k4[2]);
            }
        }

        {
            float mx = -1e30f;
            #pragma unroll
            for (int nt=0; nt<8; nt++) mx = fmaxf(mx, fmaxf(s[nt][0], s[nt][1]));
            mx = fmaxf(mx, __shfl_xor_sync(0xffffffffu, mx, 1));
            mx = fmaxf(mx, __shfl_xor_sync(0xffffffffu, mx, 2));
            float mn = fmaxf(m0r, mx);
            float corr = __expf(m0r - mn);
            m0r = mn;
            float sum = 0.f;
            #pragma unroll
            for (int nt=0; nt<8; nt++){
                float p0 = __expf(s[nt][0]-mn), p1 = __expf(s[nt][1]-mn);
                sum += p0+p1;
                *(__half2*)&sP[r0*AKV + nt*8 + pcol] = __floats2half2_rn(p0, p1);
            }
            sum += __shfl_xor_sync(0xffffffffu, sum, 1);
            sum += __shfl_xor_sync(0xffffffffu, sum, 2);
            l0r = l0r*corr + sum;
            #pragma unroll
            for (int i=0;i<8;i++){ o[i][0]*=corr; o[i][1]*=corr; }
        }
        {
            float mx = -1e30f;
            #pragma unroll
            for (int nt=0; nt<8; nt++) mx = fmaxf(mx, fmaxf(s[nt][2], s[nt][3]));
            mx = fmaxf(mx, __shfl_xor_sync(0xffffffffu, mx, 1));
            mx = fmaxf(mx, __shfl_xor_sync(0xffffffffu, mx, 2));
            float mn = fmaxf(m1r, mx);
            float corr = __expf(m1r - mn);
            m1r = mn;
            float sum = 0.f;
            #pragma unroll
            for (int nt=0; nt<8; nt++){
                float p0 = __expf(s[nt][2]-mn), p1 = __expf(s[nt][3]-mn);
                sum += p0+p1;
                *(__half2*)&sP[(r0+8)*AKV + nt*8 + pcol] = __floats2half2_rn(p0, p1);
            }
            sum += __shfl_xor_sync(0xffffffffu, sum, 1);
            sum += __shfl_xor_sync(0xffffffffu, sum, 2);
            l1r = l1r*corr + sum;
            #pragma unroll
            for (int i=0;i<8;i++){ o[i][2]*=corr; o[i][3]*=corr; }
        }
        __syncwarp();

        const uint32_t bV = sV[t&1] + bOffP;
        #pragma unroll
        for (int k16=0; k16<4; k16++){
            const uint32_t kb = k16*32;
            uint32_t pa[4];
            ldmx4(pa, aQP + kb);
            #pragma unroll
            for (int p=0; p<4; p++){
                uint32_t v4[4];
                ldmx4(v4, bV + p*(16*AKV*2) + kb);
                mmah(o[2*p],   pa, &v4[0]);
                mmah(o[2*p+1], pa, &v4[2]);
            }
        }
        if (t < 15) CP_WAIT0();
        __syncthreads();
    }

    float inv0 = 1.f/l0r, inv1 = 1.f/l1r;
    __half* ob = OutB + ((size_t)z*NHW + q0)*NC + h*HD;
    #pragma unroll
    for (int nt=0; nt<8; nt++){
        int d = nt*8 + pcol;
        *(__half2*)&ob[(size_t)r0*NC + d] =
            __floats2half2_rn(o[nt][0]*inv0, o[nt][1]*inv0);
        *(__half2*)&ob[(size_t)(r0+8)*NC + d] =
            __floats2half2_rn(o[nt][2]*inv1, o[nt][3]*inv1);
    }
}

// ============================================================================
extern "C" void kernel_launch(void* const* d_in, const int* in_sizes, int n_in,
                              void* d_out, int out_size)
{
    const float* x      = (const float*)d_in[0];
    const float* gn_w   = (const float*)d_in[1];
    const float* gn_b   = (const float*)d_in[2];
    const float* qkv_w  = (const float*)d_in[3];
    const float* qkv_b  = (const float*)d_in[4];
    const float* proj_w = (const float*)d_in[5];
    const float* proj_b = (const float*)d_in[6];
    float* out = (float*)d_out;

    __half *attB, *wAf, *wPf, *xnT, *QT, *KT, *vc;
    cudaGetSymbolAddress((void**)&attB, g_attB);
    cudaGetSymbolAddress((void**)&wAf,  g_wAf);
    cudaGetSymbolAddress((void**)&wPf,  g_wPf);
    cudaGetSymbolAddress((void**)&xnT,  g_xnT);
    cudaGetSymbolAddress((void**)&QT,   g_QT);
    cudaGetSymbolAddress((void**)&KT,   g_KT);
    cudaGetSymbolAddress((void**)&vc,   g_vc);

    static int attr_set = 0;
    if (!attr_set){
        cudaFuncSetAttribute(attn_mma_kernel,
            cudaFuncAttributeMaxDynamicSharedMemorySize, ATT_SMEM);
        cudaFuncSetAttribute(mma_gemm_kernel,
            cudaFuncAttributeMaxDynamicSharedMemorySize, GEMM_SMEM);
        attr_set = 1;
    }

    // 1. GroupNorm stats
    gn_stats_kernel<<<NB*NG, 256>>>(x);

    // 2. Weights -> fp16; fused GN-apply + transpose of x -> fp16
    conv_w_kernel<<<(3*NC*NC)/1024, 256>>>(qkv_w, wAf, 3*NC*NC);
    conv_xnT_kernel<<<dim3(32, 16, NB), dim3(32,8)>>>(x, gn_w, gn_b, xnT);

    // 3. QKV GEMM with fused Q/K/V layout epilogue (mode 1)
    mma_gemm_kernel<<<dim3(8, 12, NB), 256, GEMM_SMEM>>>(
        wAf, xnT, qkv_b, nullptr, nullptr, 3*NC, 1, QT, KT, vc);

    // 4. FP16 flash attention -> attB (proj-B fp16 layout)
    attn_mma_kernel<<<dim3(NHW/256, NB*NH), 512, ATT_SMEM>>>(QT, KT, vc, attB);

    // 5. proj weights -> fp16; proj GEMM + residual (mode 0) -> out
    conv_w_kernel<<<(NC*NC)/1024, 256>>>(proj_w, wPf, NC*NC);
    mma_gemm_kernel<<<dim3(8, 4, NB), 256, GEMM_SMEM>>>(
        wPf, attB, proj_b, x, out, NC, 0, nullptr, nullptr, nullptr);
}